// round 9
// baseline (speedup 1.0000x reference)
#include <cuda_runtime.h>
#include <cuda_fp16.h>
#include <math.h>

// Problem constants
constexpr int B   = 16;
constexpr int H   = 8;
constexpr int N1  = 256;
constexpr int N2  = 576;
constexpr int HD  = 64;
constexpr int DIM = 512;
constexpr int BH  = B * H;       // 128
constexpr int ITERS = 100;

typedef unsigned long long u64;
typedef unsigned int u32;

// ---- packed f32x2 helpers (sm_103a FFMA2; ptxas never auto-fuses) ----
__device__ __forceinline__ u64 ffma2(u64 a, u64 b, u64 c) {
    u64 d; asm("fma.rn.f32x2 %0,%1,%2,%3;" : "=l"(d) : "l"(a), "l"(b), "l"(c)); return d;
}
__device__ __forceinline__ u64 pack2(float x, float y) {
    u64 d; asm("mov.b64 %0,{%1,%2};" : "=l"(d) : "f"(x), "f"(y)); return d;
}
__device__ __forceinline__ float2 unpack2(u64 d) {
    float2 r; asm("mov.b64 {%0,%1},%2;" : "=f"(r.x), "=f"(r.y) : "l"(d)); return r;
}
// fp16x2 (as u32) -> f32x2 (as u64) with no SASS MOVs: ptxas allocates f0,f1
// as the aligned destination pair and elides the pack movs -> 2x F2F only.
__device__ __forceinline__ u64 h2_to_f2(u32 h) {
    u64 out;
    asm("{\n\t"
        ".reg .b16 h0,h1;\n\t"
        ".reg .f32 f0,f1;\n\t"
        "mov.b32 {h0,h1}, %1;\n\t"
        "cvt.f32.f16 f0, h0;\n\t"
        "cvt.f32.f16 f1, h1;\n\t"
        "mov.b64 %0, {f0,f1};\n\t"
        "}" : "=l"(out) : "r"(h));
    return out;
}

// Static scratch (no runtime allocation allowed)
__device__ float g_q[BH * N1 * HD];
__device__ float g_k[BH * N2 * HD];
__device__ float g_v[BH * N2 * HD];
__device__ float g_sim[(size_t)BH * N1 * N2];     // fp32 sim (exact)
__device__ __half g_A16[(size_t)BH * N1 * N2];    // fp16 shifted Gibbs kernel e^(20 sim - 9)
__device__ float g_alpha[BH * N1];
__device__ float g_beta[BH * N2];
__device__ float g_ctx[B * N1 * DIM];

// ---------------------------------------------------------------------------
// fp32 GEMM, 128x128 tile, 256 threads, 8x8/thread, FFMA2 inner product.
// MODE 0: plain  out0[M,N] = X@W0^T + bias0
// MODE 1: q epilogue  — add bias, per-head (64-col quadrant) L2 norm,
//         scatter to [B,H,N1,64] layout in out0.
// MODE 2: kv epilogue — N=1024 logical; cols [0,512) from W0 (k, normalized,
//         -> out0), cols [512,1024) from W1 (v, raw -> out1), layout [B,H,N2,64].
// ---------------------------------------------------------------------------
template<int MODE>
__global__ __launch_bounds__(256) void gemm128_kernel(
    const float* __restrict__ X,
    const float* __restrict__ W0, const float* __restrict__ W1,
    const float* __restrict__ bias0, const float* __restrict__ bias1,
    float* __restrict__ out0, float* __restrict__ out1,
    int M, int N, int K)
{
    __shared__ __align__(16) float Xs[16][132];
    __shared__ __align__(16) float Ws[16][132];
    const int tid = threadIdx.x;
    const int tx = tid & 15, ty = tid >> 4;
    const int bm = blockIdx.y * 128, bn = blockIdx.x * 128;
    const int lr = tid >> 1;            // 0..127
    const int lc = (tid & 1) * 8;       // 0 or 8

    const float* Wsel;
    const float* bsel;
    if (MODE == 2 && bn >= 512) { Wsel = W1 + (size_t)(bn - 512) * K; bsel = bias1 + (bn - 512); }
    else                        { Wsel = W0 + (size_t)bn * K;         bsel = bias0 + bn; }

    u64 acc[2][2][4][2];
#pragma unroll
    for (int iq = 0; iq < 2; iq++)
#pragma unroll
        for (int jq = 0; jq < 2; jq++)
#pragma unroll
            for (int i = 0; i < 4; i++) { acc[iq][jq][i][0] = 0ull; acc[iq][jq][i][1] = 0ull; }

    const float* Xp = X + (size_t)(bm + lr) * K + lc;
    const float* Wp = Wsel + (size_t)lr * K + lc;

    for (int k0 = 0; k0 < K; k0 += 16) {
        float4 x0 = *(const float4*)(Xp + k0);
        float4 x1 = *(const float4*)(Xp + k0 + 4);
        float4 w0 = *(const float4*)(Wp + k0);
        float4 w1 = *(const float4*)(Wp + k0 + 4);
        Xs[lc + 0][lr] = x0.x; Xs[lc + 1][lr] = x0.y; Xs[lc + 2][lr] = x0.z; Xs[lc + 3][lr] = x0.w;
        Xs[lc + 4][lr] = x1.x; Xs[lc + 5][lr] = x1.y; Xs[lc + 6][lr] = x1.z; Xs[lc + 7][lr] = x1.w;
        Ws[lc + 0][lr] = w0.x; Ws[lc + 1][lr] = w0.y; Ws[lc + 2][lr] = w0.z; Ws[lc + 3][lr] = w0.w;
        Ws[lc + 4][lr] = w1.x; Ws[lc + 5][lr] = w1.y; Ws[lc + 6][lr] = w1.z; Ws[lc + 7][lr] = w1.w;
        __syncthreads();
#pragma unroll
        for (int kk = 0; kk < 16; kk++) {
            float4 a0 = *(const float4*)&Xs[kk][ty * 4];
            float4 a1 = *(const float4*)&Xs[kk][64 + ty * 4];
            float4 b0 = *(const float4*)&Ws[kk][tx * 4];
            float4 b1 = *(const float4*)&Ws[kk][64 + tx * 4];
            u64 bp[2][2] = {{pack2(b0.x, b0.y), pack2(b0.z, b0.w)},
                            {pack2(b1.x, b1.y), pack2(b1.z, b1.w)}};
            float av[2][4] = {{a0.x, a0.y, a0.z, a0.w}, {a1.x, a1.y, a1.z, a1.w}};
#pragma unroll
            for (int iq = 0; iq < 2; iq++)
#pragma unroll
                for (int i = 0; i < 4; i++) {
                    u64 ad = pack2(av[iq][i], av[iq][i]);
#pragma unroll
                    for (int jq = 0; jq < 2; jq++) {
                        acc[iq][jq][i][0] = ffma2(ad, bp[jq][0], acc[iq][jq][i][0]);
                        acc[iq][jq][i][1] = ffma2(ad, bp[jq][1], acc[iq][jq][i][1]);
                    }
                }
        }
        __syncthreads();
    }

    float4 bb0 = *(const float4*)(bsel + (tx << 2));
    float4 bb1 = *(const float4*)(bsel + 64 + (tx << 2));

    if (MODE == 0) {
#pragma unroll
        for (int iq = 0; iq < 2; iq++)
#pragma unroll
            for (int i = 0; i < 4; i++) {
                int r = bm + iq * 64 + ty * 4 + i;
#pragma unroll
                for (int jq = 0; jq < 2; jq++) {
                    int c = bn + jq * 64 + (tx << 2);
                    float4 bb = jq ? bb1 : bb0;
                    float2 p0 = unpack2(acc[iq][jq][i][0]);
                    float2 p1 = unpack2(acc[iq][jq][i][1]);
                    *(float4*)(out0 + (size_t)r * N + c) =
                        make_float4(p0.x + bb.x, p0.y + bb.y, p1.x + bb.z, p1.y + bb.w);
                }
            }
    } else {
        const bool do_norm = (MODE == 1) || (bn < 512);
#pragma unroll
        for (int iq = 0; iq < 2; iq++)
#pragma unroll
            for (int i = 0; i < 4; i++) {
                int r = bm + iq * 64 + ty * 4 + i;
                int b, nn;
                if (MODE == 1) { b = r >> 8; nn = r & 255; }
                else           { b = r / N2; nn = r - b * N2; }
#pragma unroll
                for (int jq = 0; jq < 2; jq++) {
                    float4 bb = jq ? bb1 : bb0;
                    float2 p0 = unpack2(acc[iq][jq][i][0]);
                    float2 p1 = unpack2(acc[iq][jq][i][1]);
                    float v0 = p0.x + bb.x, v1 = p0.y + bb.y;
                    float v2 = p1.x + bb.z, v3 = p1.y + bb.w;
                    float s = 1.f;
                    if (do_norm) {
                        float ss = v0 * v0 + v1 * v1 + v2 * v2 + v3 * v3;
                        ss += __shfl_xor_sync(0xffffffffu, ss, 1);
                        ss += __shfl_xor_sync(0xffffffffu, ss, 2);
                        ss += __shfl_xor_sync(0xffffffffu, ss, 4);
                        ss += __shfl_xor_sync(0xffffffffu, ss, 8);
                        s = 1.0f / fmaxf(sqrtf(ss), 1e-12f);
                    }
                    int c0 = bn + jq * 64;
                    float* dst;
                    if (MODE == 1) {
                        int h = c0 >> 6;
                        dst = out0 + ((size_t)((b * H + h) * N1 + nn)) * 64 + (tx << 2);
                    } else if (c0 < 512) {
                        int h = c0 >> 6;
                        dst = out0 + ((size_t)((b * H + h) * N2 + nn)) * 64 + (tx << 2);
                    } else {
                        int h = (c0 - 512) >> 6;
                        dst = out1 + ((size_t)((b * H + h) * N2 + nn)) * 64 + (tx << 2);
                    }
                    *(float4*)dst = make_float4(v0 * s, v1 * s, v2 * s, v3 * s);
                }
            }
    }
}

// ---------------------------------------------------------------------------
// sim = q.k (beta_t=1); store fp32 sim and fp16 shifted A = exp(20*sim - 9)
// (plain row-major A layout).
// ---------------------------------------------------------------------------
__global__ __launch_bounds__(256) void sim_kernel(
    const float* __restrict__ q, const float* __restrict__ k,
    float* __restrict__ simo, __half* __restrict__ Ao)
{
    __shared__ __align__(16) float Qs[64][68];
    __shared__ __align__(16) float Ks[64][68];
    int bh = blockIdx.z;
    int i0 = blockIdx.y * 64, j0 = blockIdx.x * 64;
    const float* qp = q + (size_t)bh * N1 * HD;
    const float* kp = k + (size_t)bh * N2 * HD;
    int tid = threadIdx.x;
    int tx = tid & 15, ty = tid >> 4;
    int lr = tid >> 2;
#pragma unroll
    for (int it = 0; it < 4; it++) {
        int lc = (((tid & 3) + (it << 2)) << 2);
        float4 qv = *(const float4*)(qp + (size_t)(i0 + lr) * HD + lc);
        Qs[lc + 0][lr] = qv.x; Qs[lc + 1][lr] = qv.y; Qs[lc + 2][lr] = qv.z; Qs[lc + 3][lr] = qv.w;
        float4 kv = *(const float4*)(kp + (size_t)(j0 + lr) * HD + lc);
        Ks[lc + 0][lr] = kv.x; Ks[lc + 1][lr] = kv.y; Ks[lc + 2][lr] = kv.z; Ks[lc + 3][lr] = kv.w;
    }
    __syncthreads();
    u64 acc2[4][2];
#pragma unroll
    for (int i = 0; i < 4; i++) { acc2[i][0] = 0ull; acc2[i][1] = 0ull; }
#pragma unroll 8
    for (int kk = 0; kk < 64; kk++) {
        float4 a = *(const float4*)&Qs[kk][ty << 2];
        float4 b = *(const float4*)&Ks[kk][tx << 2];
        u64 b01 = pack2(b.x, b.y), b23 = pack2(b.z, b.w);
        float av[4] = {a.x, a.y, a.z, a.w};
#pragma unroll
        for (int i = 0; i < 4; i++) {
            u64 ad = pack2(av[i], av[i]);
            acc2[i][0] = ffma2(ad, b01, acc2[i][0]);
            acc2[i][1] = ffma2(ad, b23, acc2[i][1]);
        }
    }
    size_t base = (size_t)bh * N1 * N2;
#pragma unroll
    for (int i = 0; i < 4; i++) {
        size_t idx = base + (size_t)(i0 + (ty << 2) + i) * N2 + (j0 + (tx << 2));
        float2 p0 = unpack2(acc2[i][0]);
        float2 p1 = unpack2(acc2[i][1]);
        *(float4*)(simo + idx) = make_float4(p0.x, p0.y, p1.x, p1.y);
        __half2* A2 = (__half2*)(Ao + idx);
        A2[0] = __floats2half2_rn(__expf(fmaf(p0.x, 20.0f, -9.0f)),
                                  __expf(fmaf(p0.y, 20.0f, -9.0f)));
        A2[1] = __floats2half2_rn(__expf(fmaf(p1.x, 20.0f, -9.0f)),
                                  __expf(fmaf(p1.y, 20.0f, -9.0f)));
    }
}

// ---------------------------------------------------------------------------
// Sinkhorn, fp16 shifted A, ONE CTA of 1024 threads (32 warps) per bh slice.
// R7-proven loop structure (8 rows/warp, unroll 4 -> 36 loads in flight),
// MOV-free fp16->f32x2 conversion. Dynamic smem for 32-warp col partials.
// ---------------------------------------------------------------------------
constexpr int SK_THREADS = 1024;
constexpr int SK_NW = SK_THREADS / 32;          // 32 warps
constexpr int SK_RPW = N1 / SK_NW;              // 8 rows per warp
constexpr int SK_CP_STRIDE = 584;               // padded col-partial stride
constexpr int SK_OFF_ALPHA = 0;                 // [256]
constexpr int SK_OFF_R     = 256;               // [256]
constexpr int SK_OFF_BETA  = 512;               // [576] (8B aligned)
constexpr int SK_OFF_CP    = 1088;              // [32][584]
constexpr int SK_SMEM_FLOATS = SK_OFF_CP + SK_NW * SK_CP_STRIDE;
constexpr int SK_SMEM_BYTES  = SK_SMEM_FLOATS * 4;   // ~79KB

__global__ __launch_bounds__(SK_THREADS, 1) void sinkhorn_kernel(
    const __half* __restrict__ A16, float* __restrict__ alpha_out,
    float* __restrict__ beta_out)
{
    extern __shared__ __align__(16) float smem[];
    float* s_alpha = smem + SK_OFF_ALPHA;
    float* s_r     = smem + SK_OFF_R;
    float* s_beta  = smem + SK_OFF_BETA;
    float* s_cpart = smem + SK_OFF_CP;

    int bh = blockIdx.x;
    const u32* A = (const u32*)(A16 + (size_t)bh * N1 * N2);  // 288 u32 per row
    int tid = threadIdx.x, lane = tid & 31, w = tid >> 5;

    for (int i = tid; i < N1; i += SK_THREADS) s_alpha[i] = 1.f;
    for (int j = tid; j < N2; j += SK_THREADS) s_beta[j] = 1.f;
    __syncthreads();

    const float MU = 1.0f / 256.0f + 1e-8f;
    const float NU = 1.0f / 576.0f + 1e-8f;

#pragma unroll 1
    for (int it = 0; it < ITERS; it++) {
        u64 pb[9], pc[9];
        const u64* sb2 = (const u64*)s_beta;
#pragma unroll
        for (int t = 0; t < 9; t++) { pb[t] = sb2[lane + 32 * t]; pc[t] = 0ull; }

#pragma unroll 4
        for (int rr = 0; rr < SK_RPW; rr++) {
            int i = w * SK_RPW + rr;
            float ai = s_alpha[i];
            u64 ad = pack2(ai, ai);
            u64 accr2 = 0ull;
            const u32* row = A + i * 288 + lane;
#pragma unroll
            for (int t = 0; t < 9; t++) {
                u32 x = row[32 * t];
                u64 a2 = h2_to_f2(x);                // 2x F2F, no MOVs
                accr2 = ffma2(a2, pb[t], accr2);     // row sum   (A beta)
                pc[t] = ffma2(a2, ad, pc[t]);        // col parts (A^T alpha)
            }
            float2 ar = unpack2(accr2);
            float accr = ar.x + ar.y;
#pragma unroll
            for (int o = 16; o > 0; o >>= 1) accr += __shfl_xor_sync(0xffffffffu, accr, o);
            if (lane == 0) s_r[i] = accr;
        }
        u64* cp2 = (u64*)(s_cpart + w * SK_CP_STRIDE);
#pragma unroll
        for (int t = 0; t < 9; t++) cp2[lane + 32 * t] = pc[t];
        __syncthreads();

        if (tid < N1) s_alpha[tid] = MU / s_r[tid];
        if (tid < N2) {
            float sc = 0.f;
#pragma unroll
            for (int ww = 0; ww < SK_NW; ww++) sc += s_cpart[ww * SK_CP_STRIDE + tid];
            s_beta[tid] = NU / sc;
        }
        __syncthreads();
    }

    for (int i = tid; i < N1; i += SK_THREADS) alpha_out[bh * N1 + i] = s_alpha[i];
    for (int j = tid; j < N2; j += SK_THREADS) beta_out[bh * N2 + j] = s_beta[j];
}

// ---------------------------------------------------------------------------
// ctx = (N1*N2 * sim * exp(20*sim-9) * alpha_n * beta_m) @ v
// (fp32 A recomputed with the SAME shift as Sinkhorn's -> consistent T.)
// ---------------------------------------------------------------------------
__global__ __launch_bounds__(256) void av_kernel(
    const float* __restrict__ sim_all, const float* __restrict__ v_all,
    const float* __restrict__ alpha, const float* __restrict__ beta,
    float* __restrict__ ctx)
{
    __shared__ __align__(16) float Ss[64][68];   // [m][n]
    __shared__ __align__(16) float Vs[64][68];   // [m][c]
    __shared__ float sa[64];
    __shared__ float sb[64];
    int bh = blockIdx.y;
    int n0 = blockIdx.x * 64;
    const float* simp = sim_all + (size_t)bh * N1 * N2;
    const float* vp   = v_all   + (size_t)bh * N2 * HD;
    int tid = threadIdx.x, tx = tid & 15, ty = tid >> 4;
    int lr = tid >> 2;

    if (tid < 64) sa[tid] = alpha[bh * N1 + n0 + tid] * 147456.0f;  // fold N1*N2

    u64 acc2[4][2];
#pragma unroll
    for (int i = 0; i < 4; i++) { acc2[i][0] = 0ull; acc2[i][1] = 0ull; }

    for (int m0 = 0; m0 < N2; m0 += 64) {
        if (tid < 64) sb[tid] = beta[bh * N2 + m0 + tid];
        __syncthreads();          // guards sa/sb visible + previous compute done
#pragma unroll
        for (int it = 0; it < 4; it++) {
            int lc = (((tid & 3) + (it << 2)) << 2);
            size_t idx = (size_t)(n0 + lr) * N2 + m0 + lc;
            float4 sv = *(const float4*)(simp + idx);
            float an = sa[lr];
            Ss[lc + 0][lr] = sv.x * __expf(fmaf(sv.x, 20.f, -9.f)) * an * sb[lc + 0];
            Ss[lc + 1][lr] = sv.y * __expf(fmaf(sv.y, 20.f, -9.f)) * an * sb[lc + 1];
            Ss[lc + 2][lr] = sv.z * __expf(fmaf(sv.z, 20.f, -9.f)) * an * sb[lc + 2];
            Ss[lc + 3][lr] = sv.w * __expf(fmaf(sv.w, 20.f, -9.f)) * an * sb[lc + 3];
            float4 vv = *(const float4*)(vp + (size_t)(m0 + lr) * HD + lc);
            *(float4*)&Vs[lr][lc] = vv;
        }
        __syncthreads();
#pragma unroll 8
        for (int kk = 0; kk < 64; kk++) {
            float4 a = *(const float4*)&Ss[kk][ty << 2];
            float4 b = *(const float4*)&Vs[kk][tx << 2];
            u64 b01 = pack2(b.x, b.y), b23 = pack2(b.z, b.w);
            float av[4] = {a.x, a.y, a.z, a.w};
#pragma unroll
            for (int i = 0; i < 4; i++) {
                u64 ad = pack2(av[i], av[i]);
                acc2[i][0] = ffma2(ad, b01, acc2[i][0]);
                acc2[i][1] = ffma2(ad, b23, acc2[i][1]);
            }
        }
    }
    int b = bh >> 3, h = bh & 7;
#pragma unroll
    for (int i = 0; i < 4; i++) {
        float2 p0 = unpack2(acc2[i][0]);
        float2 p1 = unpack2(acc2[i][1]);
        float* dst = ctx + (size_t)(b * N1 + n0 + (ty << 2) + i) * DIM + h * HD + (tx << 2);
        *(float4*)dst = make_float4(p0.x, p0.y, p1.x, p1.y);
    }
}

// ---------------------------------------------------------------------------
// In-place row L2 normalization (plain divide): rows of 512 floats
// ---------------------------------------------------------------------------
__global__ __launch_bounds__(128) void norm_rows_kernel(float* __restrict__ out)
{
    __shared__ float red[4];
    int row = blockIdx.x;
    float4* p = (float4*)(out + (size_t)row * DIM);
    int tid = threadIdx.x;
    float4 v = p[tid];
    float ss = v.x * v.x + v.y * v.y + v.z * v.z + v.w * v.w;
#pragma unroll
    for (int o = 16; o > 0; o >>= 1) ss += __shfl_xor_sync(0xffffffffu, ss, o);
    if ((tid & 31) == 0) red[tid >> 5] = ss;
    __syncthreads();
    float tot = red[0] + red[1] + red[2] + red[3];
    float inv = 1.0f / sqrtf(tot);
    v.x *= inv; v.y *= inv; v.z *= inv; v.w *= inv;
    p[tid] = v;
}

// ---------------------------------------------------------------------------
extern "C" void kernel_launch(void* const* d_in, const int* in_sizes, int n_in,
                              void* d_out, int out_size)
{
    (void)in_sizes; (void)n_in; (void)out_size;
    const float* F_t = (const float*)d_in[0];
    const float* F_s = (const float*)d_in[1];
    const float* Wq  = (const float*)d_in[2];
    const float* bq  = (const float*)d_in[3];
    const float* Wk  = (const float*)d_in[4];
    const float* bk  = (const float*)d_in[5];
    const float* Wv  = (const float*)d_in[6];
    const float* bv  = (const float*)d_in[7];
    const float* Wp  = (const float*)d_in[8];
    const float* bp  = (const float*)d_in[9];
    float* out = (float*)d_out;

    float *q, *k, *v, *simb, *alpha, *beta, *ctx;
    __half* A16;
    cudaGetSymbolAddress((void**)&q, g_q);
    cudaGetSymbolAddress((void**)&k, g_k);
    cudaGetSymbolAddress((void**)&v, g_v);
    cudaGetSymbolAddress((void**)&simb, g_sim);
    cudaGetSymbolAddress((void**)&A16, g_A16);
    cudaGetSymbolAddress((void**)&alpha, g_alpha);
    cudaGetSymbolAddress((void**)&beta, g_beta);
    cudaGetSymbolAddress((void**)&ctx, g_ctx);

    // allow ~79KB dynamic smem for the 32-warp sinkhorn (attribute set, not alloc)
    cudaFuncSetAttribute(sinkhorn_kernel,
                         cudaFuncAttributeMaxDynamicSharedMemorySize, SK_SMEM_BYTES);

    // 1) Q projection fused with transpose + per-head l2norm  -> g_q [B,H,N1,64]
    gemm128_kernel<1><<<dim3(DIM / 128, B * N1 / 128), 256>>>(
        F_t, Wq, nullptr, bq, nullptr, q, nullptr, B * N1, DIM, DIM);

    // 2) K+V fused projection (N=1024) with transpose (+norm for K)
    gemm128_kernel<2><<<dim3(1024 / 128, B * N2 / 128), 256>>>(
        F_s, Wk, Wv, bk, bv, k, v, B * N2, 1024, DIM);

    // 3) sim (fp32) + fp16 shifted Gibbs kernel A = exp(20*sim - 9)
    sim_kernel<<<dim3(N2 / 64, N1 / 64, BH), 256>>>(q, k, simb, A16);

    // 4) 100 Sinkhorn iterations, one 1024-thread CTA per (b,h)
    sinkhorn_kernel<<<BH, SK_THREADS, SK_SMEM_BYTES>>>(A16, alpha, beta);

    // 5) score @ v -> ctx [B*N1, 512]  (fp32 shifted A recomputed from sim)
    av_kernel<<<dim3(N1 / 64, BH), 256>>>(simb, v, alpha, beta, ctx);

    // 6) projection + 7) row normalize (in place in d_out)
    gemm128_kernel<0><<<dim3(DIM / 128, B * N1 / 128), 256>>>(
        ctx, Wp, nullptr, bp, nullptr, out, nullptr, B * N1, DIM, DIM);
    norm_rows_kernel<<<B * N1, 128>>>(out);
}

// round 10
// speedup vs baseline: 1.6384x; 1.6384x over previous
#include <cuda_runtime.h>
#include <cuda_fp16.h>
#include <math.h>

// Problem constants
constexpr int B   = 16;
constexpr int H   = 8;
constexpr int N1  = 256;
constexpr int N2  = 576;
constexpr int HD  = 64;
constexpr int DIM = 512;
constexpr int BH  = B * H;       // 128
constexpr int ITERS = 100;

typedef unsigned long long u64;
typedef unsigned int u32;

// ---- packed f32x2 helpers (sm_103a FFMA2; ptxas never auto-fuses) ----
__device__ __forceinline__ u64 ffma2(u64 a, u64 b, u64 c) {
    u64 d; asm("fma.rn.f32x2 %0,%1,%2,%3;" : "=l"(d) : "l"(a), "l"(b), "l"(c)); return d;
}
__device__ __forceinline__ u64 pack2(float x, float y) {
    u64 d; asm("mov.b64 %0,{%1,%2};" : "=l"(d) : "f"(x), "f"(y)); return d;
}
__device__ __forceinline__ float2 unpack2(u64 d) {
    float2 r; asm("mov.b64 {%0,%1},%2;" : "=f"(r.x), "=f"(r.y) : "l"(d)); return r;
}

// Static scratch (no runtime allocation allowed)
__device__ float g_q[BH * N1 * HD];
__device__ float g_k[BH * N2 * HD];
__device__ float g_v[BH * N2 * HD];
__device__ float g_sim[(size_t)BH * N1 * N2];     // fp32 sim (exact)
__device__ __half g_A16[(size_t)BH * N1 * N2];    // fp16 shifted Gibbs kernel e^(20 sim - 9)
__device__ float g_alpha[BH * N1];
__device__ float g_beta[BH * N2];
__device__ float g_ctx[B * N1 * DIM];

// ---------------------------------------------------------------------------
// fp32 GEMM, 128x128 tile, 256 threads, 8x8/thread, FFMA2 inner product.
// MODE 0: plain  out0[M,N] = X@W0^T + bias0
// MODE 1: q epilogue  — add bias, per-head (64-col quadrant) L2 norm,
//         scatter to [B,H,N1,64] layout in out0.
// MODE 2: kv epilogue — N=1024 logical; cols [0,512) from W0 (k, normalized,
//         -> out0), cols [512,1024) from W1 (v, raw -> out1), layout [B,H,N2,64].
// ---------------------------------------------------------------------------
template<int MODE>
__global__ __launch_bounds__(256) void gemm128_kernel(
    const float* __restrict__ X,
    const float* __restrict__ W0, const float* __restrict__ W1,
    const float* __restrict__ bias0, const float* __restrict__ bias1,
    float* __restrict__ out0, float* __restrict__ out1,
    int M, int N, int K)
{
    __shared__ __align__(16) float Xs[16][132];
    __shared__ __align__(16) float Ws[16][132];
    const int tid = threadIdx.x;
    const int tx = tid & 15, ty = tid >> 4;
    const int bm = blockIdx.y * 128, bn = blockIdx.x * 128;
    const int lr = tid >> 1;            // 0..127
    const int lc = (tid & 1) * 8;       // 0 or 8

    const float* Wsel;
    const float* bsel;
    if (MODE == 2 && bn >= 512) { Wsel = W1 + (size_t)(bn - 512) * K; bsel = bias1 + (bn - 512); }
    else                        { Wsel = W0 + (size_t)bn * K;         bsel = bias0 + bn; }

    u64 acc[2][2][4][2];
#pragma unroll
    for (int iq = 0; iq < 2; iq++)
#pragma unroll
        for (int jq = 0; jq < 2; jq++)
#pragma unroll
            for (int i = 0; i < 4; i++) { acc[iq][jq][i][0] = 0ull; acc[iq][jq][i][1] = 0ull; }

    const float* Xp = X + (size_t)(bm + lr) * K + lc;
    const float* Wp = Wsel + (size_t)lr * K + lc;

    for (int k0 = 0; k0 < K; k0 += 16) {
        float4 x0 = *(const float4*)(Xp + k0);
        float4 x1 = *(const float4*)(Xp + k0 + 4);
        float4 w0 = *(const float4*)(Wp + k0);
        float4 w1 = *(const float4*)(Wp + k0 + 4);
        Xs[lc + 0][lr] = x0.x; Xs[lc + 1][lr] = x0.y; Xs[lc + 2][lr] = x0.z; Xs[lc + 3][lr] = x0.w;
        Xs[lc + 4][lr] = x1.x; Xs[lc + 5][lr] = x1.y; Xs[lc + 6][lr] = x1.z; Xs[lc + 7][lr] = x1.w;
        Ws[lc + 0][lr] = w0.x; Ws[lc + 1][lr] = w0.y; Ws[lc + 2][lr] = w0.z; Ws[lc + 3][lr] = w0.w;
        Ws[lc + 4][lr] = w1.x; Ws[lc + 5][lr] = w1.y; Ws[lc + 6][lr] = w1.z; Ws[lc + 7][lr] = w1.w;
        __syncthreads();
#pragma unroll
        for (int kk = 0; kk < 16; kk++) {
            float4 a0 = *(const float4*)&Xs[kk][ty * 4];
            float4 a1 = *(const float4*)&Xs[kk][64 + ty * 4];
            float4 b0 = *(const float4*)&Ws[kk][tx * 4];
            float4 b1 = *(const float4*)&Ws[kk][64 + tx * 4];
            u64 bp[2][2] = {{pack2(b0.x, b0.y), pack2(b0.z, b0.w)},
                            {pack2(b1.x, b1.y), pack2(b1.z, b1.w)}};
            float av[2][4] = {{a0.x, a0.y, a0.z, a0.w}, {a1.x, a1.y, a1.z, a1.w}};
#pragma unroll
            for (int iq = 0; iq < 2; iq++)
#pragma unroll
                for (int i = 0; i < 4; i++) {
                    u64 ad = pack2(av[iq][i], av[iq][i]);
#pragma unroll
                    for (int jq = 0; jq < 2; jq++) {
                        acc[iq][jq][i][0] = ffma2(ad, bp[jq][0], acc[iq][jq][i][0]);
                        acc[iq][jq][i][1] = ffma2(ad, bp[jq][1], acc[iq][jq][i][1]);
                    }
                }
        }
        __syncthreads();
    }

    float4 bb0 = *(const float4*)(bsel + (tx << 2));
    float4 bb1 = *(const float4*)(bsel + 64 + (tx << 2));

    if (MODE == 0) {
#pragma unroll
        for (int iq = 0; iq < 2; iq++)
#pragma unroll
            for (int i = 0; i < 4; i++) {
                int r = bm + iq * 64 + ty * 4 + i;
#pragma unroll
                for (int jq = 0; jq < 2; jq++) {
                    int c = bn + jq * 64 + (tx << 2);
                    float4 bb = jq ? bb1 : bb0;
                    float2 p0 = unpack2(acc[iq][jq][i][0]);
                    float2 p1 = unpack2(acc[iq][jq][i][1]);
                    *(float4*)(out0 + (size_t)r * N + c) =
                        make_float4(p0.x + bb.x, p0.y + bb.y, p1.x + bb.z, p1.y + bb.w);
                }
            }
    } else {
        const bool do_norm = (MODE == 1) || (bn < 512);
#pragma unroll
        for (int iq = 0; iq < 2; iq++)
#pragma unroll
            for (int i = 0; i < 4; i++) {
                int r = bm + iq * 64 + ty * 4 + i;
                int b, nn;
                if (MODE == 1) { b = r >> 8; nn = r & 255; }
                else           { b = r / N2; nn = r - b * N2; }
#pragma unroll
                for (int jq = 0; jq < 2; jq++) {
                    float4 bb = jq ? bb1 : bb0;
                    float2 p0 = unpack2(acc[iq][jq][i][0]);
                    float2 p1 = unpack2(acc[iq][jq][i][1]);
                    float v0 = p0.x + bb.x, v1 = p0.y + bb.y;
                    float v2 = p1.x + bb.z, v3 = p1.y + bb.w;
                    float s = 1.f;
                    if (do_norm) {
                        float ss = v0 * v0 + v1 * v1 + v2 * v2 + v3 * v3;
                        ss += __shfl_xor_sync(0xffffffffu, ss, 1);
                        ss += __shfl_xor_sync(0xffffffffu, ss, 2);
                        ss += __shfl_xor_sync(0xffffffffu, ss, 4);
                        ss += __shfl_xor_sync(0xffffffffu, ss, 8);
                        s = 1.0f / fmaxf(sqrtf(ss), 1e-12f);
                    }
                    int c0 = bn + jq * 64;
                    float* dst;
                    if (MODE == 1) {
                        int h = c0 >> 6;
                        dst = out0 + ((size_t)((b * H + h) * N1 + nn)) * 64 + (tx << 2);
                    } else if (c0 < 512) {
                        int h = c0 >> 6;
                        dst = out0 + ((size_t)((b * H + h) * N2 + nn)) * 64 + (tx << 2);
                    } else {
                        int h = (c0 - 512) >> 6;
                        dst = out1 + ((size_t)((b * H + h) * N2 + nn)) * 64 + (tx << 2);
                    }
                    *(float4*)dst = make_float4(v0 * s, v1 * s, v2 * s, v3 * s);
                }
            }
    }
}

// ---------------------------------------------------------------------------
// sim = q.k (beta_t=1); store fp32 sim and fp16 shifted A = exp(20*sim - 9)
// (plain row-major A layout).
// ---------------------------------------------------------------------------
__global__ __launch_bounds__(256) void sim_kernel(
    const float* __restrict__ q, const float* __restrict__ k,
    float* __restrict__ simo, __half* __restrict__ Ao)
{
    __shared__ __align__(16) float Qs[64][68];
    __shared__ __align__(16) float Ks[64][68];
    int bh = blockIdx.z;
    int i0 = blockIdx.y * 64, j0 = blockIdx.x * 64;
    const float* qp = q + (size_t)bh * N1 * HD;
    const float* kp = k + (size_t)bh * N2 * HD;
    int tid = threadIdx.x;
    int tx = tid & 15, ty = tid >> 4;
    int lr = tid >> 2;
#pragma unroll
    for (int it = 0; it < 4; it++) {
        int lc = (((tid & 3) + (it << 2)) << 2);
        float4 qv = *(const float4*)(qp + (size_t)(i0 + lr) * HD + lc);
        Qs[lc + 0][lr] = qv.x; Qs[lc + 1][lr] = qv.y; Qs[lc + 2][lr] = qv.z; Qs[lc + 3][lr] = qv.w;
        float4 kv = *(const float4*)(kp + (size_t)(j0 + lr) * HD + lc);
        Ks[lc + 0][lr] = kv.x; Ks[lc + 1][lr] = kv.y; Ks[lc + 2][lr] = kv.z; Ks[lc + 3][lr] = kv.w;
    }
    __syncthreads();
    u64 acc2[4][2];
#pragma unroll
    for (int i = 0; i < 4; i++) { acc2[i][0] = 0ull; acc2[i][1] = 0ull; }
#pragma unroll 8
    for (int kk = 0; kk < 64; kk++) {
        float4 a = *(const float4*)&Qs[kk][ty << 2];
        float4 b = *(const float4*)&Ks[kk][tx << 2];
        u64 b01 = pack2(b.x, b.y), b23 = pack2(b.z, b.w);
        float av[4] = {a.x, a.y, a.z, a.w};
#pragma unroll
        for (int i = 0; i < 4; i++) {
            u64 ad = pack2(av[i], av[i]);
            acc2[i][0] = ffma2(ad, b01, acc2[i][0]);
            acc2[i][1] = ffma2(ad, b23, acc2[i][1]);
        }
    }
    size_t base = (size_t)bh * N1 * N2;
#pragma unroll
    for (int i = 0; i < 4; i++) {
        size_t idx = base + (size_t)(i0 + (ty << 2) + i) * N2 + (j0 + (tx << 2));
        float2 p0 = unpack2(acc2[i][0]);
        float2 p1 = unpack2(acc2[i][1]);
        *(float4*)(simo + idx) = make_float4(p0.x, p0.y, p1.x, p1.y);
        __half2* A2 = (__half2*)(Ao + idx);
        A2[0] = __floats2half2_rn(__expf(fmaf(p0.x, 20.0f, -9.0f)),
                                  __expf(fmaf(p0.y, 20.0f, -9.0f)));
        A2[1] = __floats2half2_rn(__expf(fmaf(p1.x, 20.0f, -9.0f)),
                                  __expf(fmaf(p1.y, 20.0f, -9.0f)));
    }
}

// ---------------------------------------------------------------------------
// Sinkhorn, fp16 shifted A, ONE CTA of 1024 threads (32 warps) per bh slice.
// R7-proven loop structure (8 rows/warp, unroll 4 -> 36 loads in flight).
// fp16->f32x2 conversion WITHOUT F2F: for positive h,
//   as_float(h<<13) == value(h) * 2^-112   (exact, subnormals included).
// The 2^112 is compensated by pre-scaling alpha/beta by 2^56 and folding
// 2^-56 into MU/NU -> all math bit-equivalent up to exact powers of 2.
// Conversion = 4 ALU ops (SHF/LOP3) per u32, off the busy cvt pipe.
// ---------------------------------------------------------------------------
constexpr int SK_THREADS = 1024;
constexpr int SK_NW = SK_THREADS / 32;          // 32 warps
constexpr int SK_RPW = N1 / SK_NW;              // 8 rows per warp
constexpr int SK_CP_STRIDE = 584;               // padded col-partial stride
constexpr int SK_OFF_ALPHA = 0;                 // [256]
constexpr int SK_OFF_R     = 256;               // [256]
constexpr int SK_OFF_BETA  = 512;               // [576] (8B aligned)
constexpr int SK_OFF_CP    = 1088;              // [32][584]
constexpr int SK_SMEM_FLOATS = SK_OFF_CP + SK_NW * SK_CP_STRIDE;
constexpr int SK_SMEM_BYTES  = SK_SMEM_FLOATS * 4;   // ~79KB

__global__ __launch_bounds__(SK_THREADS, 1) void sinkhorn_kernel(
    const __half* __restrict__ A16, float* __restrict__ alpha_out,
    float* __restrict__ beta_out)
{
    extern __shared__ __align__(16) float smem[];
    float* s_alpha = smem + SK_OFF_ALPHA;
    float* s_r     = smem + SK_OFF_R;
    float* s_beta  = smem + SK_OFF_BETA;
    float* s_cpart = smem + SK_OFF_CP;

    int bh = blockIdx.x;
    const u32* A = (const u32*)(A16 + (size_t)bh * N1 * N2);  // 288 u32 per row
    int tid = threadIdx.x, lane = tid & 31, w = tid >> 5;

    for (int i = tid; i < N1; i += SK_THREADS) s_alpha[i] = 1.f;
    for (int j = tid; j < N2; j += SK_THREADS) s_beta[j] = 1.f;
    __syncthreads();

    const float SC56  = 7.2057594037927936e16f;   // 2^56 (exact)
    const float MU_S  = (1.0f / 256.0f + 1e-8f) * 1.3877787807814457e-17f;  // MU * 2^-56
    const float NU_S  = (1.0f / 576.0f + 1e-8f) * 1.3877787807814457e-17f;  // NU * 2^-56
    const u64 C56 = pack2(SC56, SC56);
    const u64 ZERO2 = 0ull;

#pragma unroll 1
    for (int it = 0; it < ITERS; it++) {
        u64 pb[9], pc[9];
        const u64* sb2 = (const u64*)s_beta;
#pragma unroll
        for (int t = 0; t < 9; t++) {
            pb[t] = ffma2(sb2[lane + 32 * t], C56, ZERO2);   // beta * 2^56
            pc[t] = 0ull;
        }

#pragma unroll 4
        for (int rr = 0; rr < SK_RPW; rr++) {
            int i = w * SK_RPW + rr;
            float ais = s_alpha[i] * SC56;                   // alpha * 2^56
            u64 ad = pack2(ais, ais);
            u64 accr2 = 0ull;
            const u32* row = A + i * 288 + lane;
#pragma unroll
            for (int t = 0; t < 9; t++) {
                u32 x = row[32 * t];
                u32 lo = (x << 13) & 0x1fffe000u;            // h0 -> f32 bits * 2^-112
                u32 hi = (x >> 3)  & 0x1fffe000u;            // h1 -> f32 bits * 2^-112
                u64 a2 = ((u64)hi << 32) | (u64)lo;
                accr2 = ffma2(a2, pb[t], accr2);             // (A*2^-112)(b*2^56) = Ab*2^-56
                pc[t] = ffma2(a2, ad, pc[t]);                // col parts * 2^-56
            }
            float2 ar = unpack2(accr2);
            float accr = ar.x + ar.y;
#pragma unroll
            for (int o = 16; o > 0; o >>= 1) accr += __shfl_xor_sync(0xffffffffu, accr, o);
            if (lane == 0) s_r[i] = accr;                    // rowsum * 2^-56
        }
        u64* cp2 = (u64*)(s_cpart + w * SK_CP_STRIDE);
#pragma unroll
        for (int t = 0; t < 9; t++) cp2[lane + 32 * t] = pc[t];
        __syncthreads();

        if (tid < N1) s_alpha[tid] = MU_S / s_r[tid];        // = MU / rowsum (true alpha)
        if (tid < N2) {
            float sc = 0.f;
#pragma unroll
            for (int ww = 0; ww < SK_NW; ww++) sc += s_cpart[ww * SK_CP_STRIDE + tid];
            s_beta[tid] = NU_S / sc;                         // = NU / colsum (true beta)
        }
        __syncthreads();
    }

    for (int i = tid; i < N1; i += SK_THREADS) alpha_out[bh * N1 + i] = s_alpha[i];
    for (int j = tid; j < N2; j += SK_THREADS) beta_out[bh * N2 + j] = s_beta[j];
}

// ---------------------------------------------------------------------------
// ctx = (N1*N2 * sim * exp(20*sim-9) * alpha_n * beta_m) @ v
// (fp32 A recomputed with the SAME shift as Sinkhorn's -> consistent T.)
// ---------------------------------------------------------------------------
__global__ __launch_bounds__(256) void av_kernel(
    const float* __restrict__ sim_all, const float* __restrict__ v_all,
    const float* __restrict__ alpha, const float* __restrict__ beta,
    float* __restrict__ ctx)
{
    __shared__ __align__(16) float Ss[64][68];   // [m][n]
    __shared__ __align__(16) float Vs[64][68];   // [m][c]
    __shared__ float sa[64];
    __shared__ float sb[64];
    int bh = blockIdx.y;
    int n0 = blockIdx.x * 64;
    const float* simp = sim_all + (size_t)bh * N1 * N2;
    const float* vp   = v_all   + (size_t)bh * N2 * HD;
    int tid = threadIdx.x, tx = tid & 15, ty = tid >> 4;
    int lr = tid >> 2;

    if (tid < 64) sa[tid] = alpha[bh * N1 + n0 + tid] * 147456.0f;  // fold N1*N2

    u64 acc2[4][2];
#pragma unroll
    for (int i = 0; i < 4; i++) { acc2[i][0] = 0ull; acc2[i][1] = 0ull; }

    for (int m0 = 0; m0 < N2; m0 += 64) {
        if (tid < 64) sb[tid] = beta[bh * N2 + m0 + tid];
        __syncthreads();          // guards sa/sb visible + previous compute done
#pragma unroll
        for (int it = 0; it < 4; it++) {
            int lc = (((tid & 3) + (it << 2)) << 2);
            size_t idx = (size_t)(n0 + lr) * N2 + m0 + lc;
            float4 sv = *(const float4*)(simp + idx);
            float an = sa[lr];
            Ss[lc + 0][lr] = sv.x * __expf(fmaf(sv.x, 20.f, -9.f)) * an * sb[lc + 0];
            Ss[lc + 1][lr] = sv.y * __expf(fmaf(sv.y, 20.f, -9.f)) * an * sb[lc + 1];
            Ss[lc + 2][lr] = sv.z * __expf(fmaf(sv.z, 20.f, -9.f)) * an * sb[lc + 2];
            Ss[lc + 3][lr] = sv.w * __expf(fmaf(sv.w, 20.f, -9.f)) * an * sb[lc + 3];
            float4 vv = *(const float4*)(vp + (size_t)(m0 + lr) * HD + lc);
            *(float4*)&Vs[lr][lc] = vv;
        }
        __syncthreads();
#pragma unroll 8
        for (int kk = 0; kk < 64; kk++) {
            float4 a = *(const float4*)&Ss[kk][ty << 2];
            float4 b = *(const float4*)&Vs[kk][tx << 2];
            u64 b01 = pack2(b.x, b.y), b23 = pack2(b.z, b.w);
            float av[4] = {a.x, a.y, a.z, a.w};
#pragma unroll
            for (int i = 0; i < 4; i++) {
                u64 ad = pack2(av[i], av[i]);
                acc2[i][0] = ffma2(ad, b01, acc2[i][0]);
                acc2[i][1] = ffma2(ad, b23, acc2[i][1]);
            }
        }
    }
    int b = bh >> 3, h = bh & 7;
#pragma unroll
    for (int i = 0; i < 4; i++) {
        float2 p0 = unpack2(acc2[i][0]);
        float2 p1 = unpack2(acc2[i][1]);
        float* dst = ctx + (size_t)(b * N1 + n0 + (ty << 2) + i) * DIM + h * HD + (tx << 2);
        *(float4*)dst = make_float4(p0.x, p0.y, p1.x, p1.y);
    }
}

// ---------------------------------------------------------------------------
// In-place row L2 normalization (plain divide): rows of 512 floats
// ---------------------------------------------------------------------------
__global__ __launch_bounds__(128) void norm_rows_kernel(float* __restrict__ out)
{
    __shared__ float red[4];
    int row = blockIdx.x;
    float4* p = (float4*)(out + (size_t)row * DIM);
    int tid = threadIdx.x;
    float4 v = p[tid];
    float ss = v.x * v.x + v.y * v.y + v.z * v.z + v.w * v.w;
#pragma unroll
    for (int o = 16; o > 0; o >>= 1) ss += __shfl_xor_sync(0xffffffffu, ss, o);
    if ((tid & 31) == 0) red[tid >> 5] = ss;
    __syncthreads();
    float tot = red[0] + red[1] + red[2] + red[3];
    float inv = 1.0f / sqrtf(tot);
    v.x *= inv; v.y *= inv; v.z *= inv; v.w *= inv;
    p[tid] = v;
}

// ---------------------------------------------------------------------------
extern "C" void kernel_launch(void* const* d_in, const int* in_sizes, int n_in,
                              void* d_out, int out_size)
{
    (void)in_sizes; (void)n_in; (void)out_size;
    const float* F_t = (const float*)d_in[0];
    const float* F_s = (const float*)d_in[1];
    const float* Wq  = (const float*)d_in[2];
    const float* bq  = (const float*)d_in[3];
    const float* Wk  = (const float*)d_in[4];
    const float* bk  = (const float*)d_in[5];
    const float* Wv  = (const float*)d_in[6];
    const float* bv  = (const float*)d_in[7];
    const float* Wp  = (const float*)d_in[8];
    const float* bp  = (const float*)d_in[9];
    float* out = (float*)d_out;

    float *q, *k, *v, *simb, *alpha, *beta, *ctx;
    __half* A16;
    cudaGetSymbolAddress((void**)&q, g_q);
    cudaGetSymbolAddress((void**)&k, g_k);
    cudaGetSymbolAddress((void**)&v, g_v);
    cudaGetSymbolAddress((void**)&simb, g_sim);
    cudaGetSymbolAddress((void**)&A16, g_A16);
    cudaGetSymbolAddress((void**)&alpha, g_alpha);
    cudaGetSymbolAddress((void**)&beta, g_beta);
    cudaGetSymbolAddress((void**)&ctx, g_ctx);

    // allow ~79KB dynamic smem for the 32-warp sinkhorn (attribute set, not alloc)
    cudaFuncSetAttribute(sinkhorn_kernel,
                         cudaFuncAttributeMaxDynamicSharedMemorySize, SK_SMEM_BYTES);

    // 1) Q projection fused with transpose + per-head l2norm  -> g_q [B,H,N1,64]
    gemm128_kernel<1><<<dim3(DIM / 128, B * N1 / 128), 256>>>(
        F_t, Wq, nullptr, bq, nullptr, q, nullptr, B * N1, DIM, DIM);

    // 2) K+V fused projection (N=1024) with transpose (+norm for K)
    gemm128_kernel<2><<<dim3(1024 / 128, B * N2 / 128), 256>>>(
        F_s, Wk, Wv, bk, bv, k, v, B * N2, 1024, DIM);

    // 3) sim (fp32) + fp16 shifted Gibbs kernel A = exp(20*sim - 9)
    sim_kernel<<<dim3(N2 / 64, N1 / 64, BH), 256>>>(q, k, simb, A16);

    // 4) 100 Sinkhorn iterations, one 1024-thread CTA per (b,h)
    sinkhorn_kernel<<<BH, SK_THREADS, SK_SMEM_BYTES>>>(A16, alpha, beta);

    // 5) score @ v -> ctx [B*N1, 512]  (fp32 shifted A recomputed from sim)
    av_kernel<<<dim3(N1 / 64, BH), 256>>>(simb, v, alpha, beta, ctx);

    // 6) projection + 7) row normalize (in place in d_out)
    gemm128_kernel<0><<<dim3(DIM / 128, B * N1 / 128), 256>>>(
        ctx, Wp, nullptr, bp, nullptr, out, nullptr, B * N1, DIM, DIM);
    norm_rows_kernel<<<B * N1, 128>>>(out);
}

// round 11
// speedup vs baseline: 1.6448x; 1.0039x over previous
#include <cuda_runtime.h>
#include <cuda_fp16.h>
#include <math.h>

// Problem constants
constexpr int B   = 16;
constexpr int H   = 8;
constexpr int N1  = 256;
constexpr int N2  = 576;
constexpr int HD  = 64;
constexpr int DIM = 512;
constexpr int BH  = B * H;       // 128
constexpr int ITERS = 100;

typedef unsigned long long u64;
typedef unsigned int u32;

// ---- packed f32x2 helpers (sm_103a FFMA2; ptxas never auto-fuses) ----
__device__ __forceinline__ u64 ffma2(u64 a, u64 b, u64 c) {
    u64 d; asm("fma.rn.f32x2 %0,%1,%2,%3;" : "=l"(d) : "l"(a), "l"(b), "l"(c)); return d;
}
__device__ __forceinline__ u64 pack2(float x, float y) {
    u64 d; asm("mov.b64 %0,{%1,%2};" : "=l"(d) : "f"(x), "f"(y)); return d;
}
__device__ __forceinline__ float2 unpack2(u64 d) {
    float2 r; asm("mov.b64 {%0,%1},%2;" : "=f"(r.x), "=f"(r.y) : "l"(d)); return r;
}

// Static scratch (no runtime allocation allowed)
__device__ float g_q[BH * N1 * HD];
__device__ float g_k[BH * N2 * HD];
__device__ float g_v[BH * N2 * HD];
__device__ float g_sim[(size_t)BH * N1 * N2];     // fp32 sim (exact)
__device__ __half g_A16[(size_t)BH * N1 * N2];    // fp16 shifted Gibbs kernel e^(20 sim - 9)
__device__ float g_alpha[BH * N1];
__device__ float g_beta[BH * N2];
__device__ float g_ctx[B * N1 * DIM];

// ---------------------------------------------------------------------------
// fp32 GEMM, 128x128 tile, 256 threads, 8x8/thread, FFMA2 inner product.
// MODE 0: plain  out0[M,N] = X@W0^T + bias0
// MODE 1: q epilogue  — add bias, per-head (64-col quadrant) L2 norm,
//         scatter to [B,H,N1,64] layout in out0.
// MODE 2: kv epilogue — N=1024 logical; cols [0,512) from W0 (k, normalized,
//         -> out0), cols [512,1024) from W1 (v, raw -> out1), layout [B,H,N2,64].
// ---------------------------------------------------------------------------
template<int MODE>
__global__ __launch_bounds__(256) void gemm128_kernel(
    const float* __restrict__ X,
    const float* __restrict__ W0, const float* __restrict__ W1,
    const float* __restrict__ bias0, const float* __restrict__ bias1,
    float* __restrict__ out0, float* __restrict__ out1,
    int M, int N, int K)
{
    __shared__ __align__(16) float Xs[16][132];
    __shared__ __align__(16) float Ws[16][132];
    const int tid = threadIdx.x;
    const int tx = tid & 15, ty = tid >> 4;
    const int bm = blockIdx.y * 128, bn = blockIdx.x * 128;
    const int lr = tid >> 1;            // 0..127
    const int lc = (tid & 1) * 8;       // 0 or 8

    const float* Wsel;
    const float* bsel;
    if (MODE == 2 && bn >= 512) { Wsel = W1 + (size_t)(bn - 512) * K; bsel = bias1 + (bn - 512); }
    else                        { Wsel = W0 + (size_t)bn * K;         bsel = bias0 + bn; }

    u64 acc[2][2][4][2];
#pragma unroll
    for (int iq = 0; iq < 2; iq++)
#pragma unroll
        for (int jq = 0; jq < 2; jq++)
#pragma unroll
            for (int i = 0; i < 4; i++) { acc[iq][jq][i][0] = 0ull; acc[iq][jq][i][1] = 0ull; }

    const float* Xp = X + (size_t)(bm + lr) * K + lc;
    const float* Wp = Wsel + (size_t)lr * K + lc;

    for (int k0 = 0; k0 < K; k0 += 16) {
        float4 x0 = *(const float4*)(Xp + k0);
        float4 x1 = *(const float4*)(Xp + k0 + 4);
        float4 w0 = *(const float4*)(Wp + k0);
        float4 w1 = *(const float4*)(Wp + k0 + 4);
        Xs[lc + 0][lr] = x0.x; Xs[lc + 1][lr] = x0.y; Xs[lc + 2][lr] = x0.z; Xs[lc + 3][lr] = x0.w;
        Xs[lc + 4][lr] = x1.x; Xs[lc + 5][lr] = x1.y; Xs[lc + 6][lr] = x1.z; Xs[lc + 7][lr] = x1.w;
        Ws[lc + 0][lr] = w0.x; Ws[lc + 1][lr] = w0.y; Ws[lc + 2][lr] = w0.z; Ws[lc + 3][lr] = w0.w;
        Ws[lc + 4][lr] = w1.x; Ws[lc + 5][lr] = w1.y; Ws[lc + 6][lr] = w1.z; Ws[lc + 7][lr] = w1.w;
        __syncthreads();
#pragma unroll
        for (int kk = 0; kk < 16; kk++) {
            float4 a0 = *(const float4*)&Xs[kk][ty * 4];
            float4 a1 = *(const float4*)&Xs[kk][64 + ty * 4];
            float4 b0 = *(const float4*)&Ws[kk][tx * 4];
            float4 b1 = *(const float4*)&Ws[kk][64 + tx * 4];
            u64 bp[2][2] = {{pack2(b0.x, b0.y), pack2(b0.z, b0.w)},
                            {pack2(b1.x, b1.y), pack2(b1.z, b1.w)}};
            float av[2][4] = {{a0.x, a0.y, a0.z, a0.w}, {a1.x, a1.y, a1.z, a1.w}};
#pragma unroll
            for (int iq = 0; iq < 2; iq++)
#pragma unroll
                for (int i = 0; i < 4; i++) {
                    u64 ad = pack2(av[iq][i], av[iq][i]);
#pragma unroll
                    for (int jq = 0; jq < 2; jq++) {
                        acc[iq][jq][i][0] = ffma2(ad, bp[jq][0], acc[iq][jq][i][0]);
                        acc[iq][jq][i][1] = ffma2(ad, bp[jq][1], acc[iq][jq][i][1]);
                    }
                }
        }
        __syncthreads();
    }

    float4 bb0 = *(const float4*)(bsel + (tx << 2));
    float4 bb1 = *(const float4*)(bsel + 64 + (tx << 2));

    if (MODE == 0) {
#pragma unroll
        for (int iq = 0; iq < 2; iq++)
#pragma unroll
            for (int i = 0; i < 4; i++) {
                int r = bm + iq * 64 + ty * 4 + i;
#pragma unroll
                for (int jq = 0; jq < 2; jq++) {
                    int c = bn + jq * 64 + (tx << 2);
                    float4 bb = jq ? bb1 : bb0;
                    float2 p0 = unpack2(acc[iq][jq][i][0]);
                    float2 p1 = unpack2(acc[iq][jq][i][1]);
                    *(float4*)(out0 + (size_t)r * N + c) =
                        make_float4(p0.x + bb.x, p0.y + bb.y, p1.x + bb.z, p1.y + bb.w);
                }
            }
    } else {
        const bool do_norm = (MODE == 1) || (bn < 512);
#pragma unroll
        for (int iq = 0; iq < 2; iq++)
#pragma unroll
            for (int i = 0; i < 4; i++) {
                int r = bm + iq * 64 + ty * 4 + i;
                int b, nn;
                if (MODE == 1) { b = r >> 8; nn = r & 255; }
                else           { b = r / N2; nn = r - b * N2; }
#pragma unroll
                for (int jq = 0; jq < 2; jq++) {
                    float4 bb = jq ? bb1 : bb0;
                    float2 p0 = unpack2(acc[iq][jq][i][0]);
                    float2 p1 = unpack2(acc[iq][jq][i][1]);
                    float v0 = p0.x + bb.x, v1 = p0.y + bb.y;
                    float v2 = p1.x + bb.z, v3 = p1.y + bb.w;
                    float s = 1.f;
                    if (do_norm) {
                        float ss = v0 * v0 + v1 * v1 + v2 * v2 + v3 * v3;
                        ss += __shfl_xor_sync(0xffffffffu, ss, 1);
                        ss += __shfl_xor_sync(0xffffffffu, ss, 2);
                        ss += __shfl_xor_sync(0xffffffffu, ss, 4);
                        ss += __shfl_xor_sync(0xffffffffu, ss, 8);
                        s = 1.0f / fmaxf(sqrtf(ss), 1e-12f);
                    }
                    int c0 = bn + jq * 64;
                    float* dst;
                    if (MODE == 1) {
                        int h = c0 >> 6;
                        dst = out0 + ((size_t)((b * H + h) * N1 + nn)) * 64 + (tx << 2);
                    } else if (c0 < 512) {
                        int h = c0 >> 6;
                        dst = out0 + ((size_t)((b * H + h) * N2 + nn)) * 64 + (tx << 2);
                    } else {
                        int h = (c0 - 512) >> 6;
                        dst = out1 + ((size_t)((b * H + h) * N2 + nn)) * 64 + (tx << 2);
                    }
                    *(float4*)dst = make_float4(v0 * s, v1 * s, v2 * s, v3 * s);
                }
            }
    }
}

// ---------------------------------------------------------------------------
// sim = q.k (beta_t=1); store fp32 sim and fp16 shifted A = exp(20*sim - 9)
// (plain row-major A layout).
// ---------------------------------------------------------------------------
__global__ __launch_bounds__(256) void sim_kernel(
    const float* __restrict__ q, const float* __restrict__ k,
    float* __restrict__ simo, __half* __restrict__ Ao)
{
    __shared__ __align__(16) float Qs[64][68];
    __shared__ __align__(16) float Ks[64][68];
    int bh = blockIdx.z;
    int i0 = blockIdx.y * 64, j0 = blockIdx.x * 64;
    const float* qp = q + (size_t)bh * N1 * HD;
    const float* kp = k + (size_t)bh * N2 * HD;
    int tid = threadIdx.x;
    int tx = tid & 15, ty = tid >> 4;
    int lr = tid >> 2;
#pragma unroll
    for (int it = 0; it < 4; it++) {
        int lc = (((tid & 3) + (it << 2)) << 2);
        float4 qv = *(const float4*)(qp + (size_t)(i0 + lr) * HD + lc);
        Qs[lc + 0][lr] = qv.x; Qs[lc + 1][lr] = qv.y; Qs[lc + 2][lr] = qv.z; Qs[lc + 3][lr] = qv.w;
        float4 kv = *(const float4*)(kp + (size_t)(j0 + lr) * HD + lc);
        Ks[lc + 0][lr] = kv.x; Ks[lc + 1][lr] = kv.y; Ks[lc + 2][lr] = kv.z; Ks[lc + 3][lr] = kv.w;
    }
    __syncthreads();
    u64 acc2[4][2];
#pragma unroll
    for (int i = 0; i < 4; i++) { acc2[i][0] = 0ull; acc2[i][1] = 0ull; }
#pragma unroll 8
    for (int kk = 0; kk < 64; kk++) {
        float4 a = *(const float4*)&Qs[kk][ty << 2];
        float4 b = *(const float4*)&Ks[kk][tx << 2];
        u64 b01 = pack2(b.x, b.y), b23 = pack2(b.z, b.w);
        float av[4] = {a.x, a.y, a.z, a.w};
#pragma unroll
        for (int i = 0; i < 4; i++) {
            u64 ad = pack2(av[i], av[i]);
            acc2[i][0] = ffma2(ad, b01, acc2[i][0]);
            acc2[i][1] = ffma2(ad, b23, acc2[i][1]);
        }
    }
    size_t base = (size_t)bh * N1 * N2;
#pragma unroll
    for (int i = 0; i < 4; i++) {
        size_t idx = base + (size_t)(i0 + (ty << 2) + i) * N2 + (j0 + (tx << 2));
        float2 p0 = unpack2(acc2[i][0]);
        float2 p1 = unpack2(acc2[i][1]);
        *(float4*)(simo + idx) = make_float4(p0.x, p0.y, p1.x, p1.y);
        __half2* A2 = (__half2*)(Ao + idx);
        A2[0] = __floats2half2_rn(__expf(fmaf(p0.x, 20.0f, -9.0f)),
                                  __expf(fmaf(p0.y, 20.0f, -9.0f)));
        A2[1] = __floats2half2_rn(__expf(fmaf(p1.x, 20.0f, -9.0f)),
                                  __expf(fmaf(p1.y, 20.0f, -9.0f)));
    }
}

// ---------------------------------------------------------------------------
// Sinkhorn, fp16 shifted A, ONE CTA of 1024 threads (32 warps) per bh slice.
// R10 structure; conversion pipe-balanced: the lo-half shift uses IMAD
// (mad.lo.u32 x*8192, fma pipe) instead of SHF (alu pipe), so per u32:
//   fma pipe: 1 IMAD + 2 FFMA2,  alu pipe: 1 SHF + 2 LOP3  (balanced 3/3).
// Bit-identical math; compensation scaling unchanged (2^56 trick).
// ---------------------------------------------------------------------------
constexpr int SK_THREADS = 1024;
constexpr int SK_NW = SK_THREADS / 32;          // 32 warps
constexpr int SK_RPW = N1 / SK_NW;              // 8 rows per warp
constexpr int SK_CP_STRIDE = 584;               // padded col-partial stride
constexpr int SK_OFF_ALPHA = 0;                 // [256]
constexpr int SK_OFF_R     = 256;               // [256]
constexpr int SK_OFF_BETA  = 512;               // [576] (8B aligned)
constexpr int SK_OFF_CP    = 1088;              // [32][584]
constexpr int SK_SMEM_FLOATS = SK_OFF_CP + SK_NW * SK_CP_STRIDE;
constexpr int SK_SMEM_BYTES  = SK_SMEM_FLOATS * 4;   // ~79KB

__global__ __launch_bounds__(SK_THREADS, 1) void sinkhorn_kernel(
    const __half* __restrict__ A16, float* __restrict__ alpha_out,
    float* __restrict__ beta_out)
{
    extern __shared__ __align__(16) float smem[];
    float* s_alpha = smem + SK_OFF_ALPHA;
    float* s_r     = smem + SK_OFF_R;
    float* s_beta  = smem + SK_OFF_BETA;
    float* s_cpart = smem + SK_OFF_CP;

    int bh = blockIdx.x;
    const u32* A = (const u32*)(A16 + (size_t)bh * N1 * N2);  // 288 u32 per row
    int tid = threadIdx.x, lane = tid & 31, w = tid >> 5;

    for (int i = tid; i < N1; i += SK_THREADS) s_alpha[i] = 1.f;
    for (int j = tid; j < N2; j += SK_THREADS) s_beta[j] = 1.f;
    __syncthreads();

    const float SC56  = 7.2057594037927936e16f;   // 2^56 (exact)
    const float MU_S  = (1.0f / 256.0f + 1e-8f) * 1.3877787807814457e-17f;  // MU * 2^-56
    const float NU_S  = (1.0f / 576.0f + 1e-8f) * 1.3877787807814457e-17f;  // NU * 2^-56
    const u64 C56 = pack2(SC56, SC56);
    const u64 ZERO2 = 0ull;
    // loop-invariant registers for the IMAD shift (keep off the alu pipe)
    u32 kMul = 8192u, kZero = 0u;

#pragma unroll 1
    for (int it = 0; it < ITERS; it++) {
        u64 pb[9], pc[9];
        const u64* sb2 = (const u64*)s_beta;
#pragma unroll
        for (int t = 0; t < 9; t++) {
            pb[t] = ffma2(sb2[lane + 32 * t], C56, ZERO2);   // beta * 2^56
            pc[t] = 0ull;
        }

#pragma unroll 4
        for (int rr = 0; rr < SK_RPW; rr++) {
            int i = w * SK_RPW + rr;
            float ais = s_alpha[i] * SC56;                   // alpha * 2^56
            u64 ad = pack2(ais, ais);
            u64 accr2 = 0ull;
            const u32* row = A + i * 288 + lane;
#pragma unroll
            for (int t = 0; t < 9; t++) {
                u32 x = row[32 * t];
                u32 sh;                                      // x<<13 via IMAD (fma pipe)
                asm("mad.lo.u32 %0,%1,%2,%3;" : "=r"(sh) : "r"(x), "r"(kMul), "r"(kZero));
                u32 lo = sh & 0x1fffe000u;                   // h0 -> f32 bits * 2^-112
                u32 hi = (x >> 3) & 0x1fffe000u;             // h1 -> f32 bits * 2^-112
                u64 a2 = ((u64)hi << 32) | (u64)lo;
                accr2 = ffma2(a2, pb[t], accr2);             // (A*2^-112)(b*2^56) = Ab*2^-56
                pc[t] = ffma2(a2, ad, pc[t]);                // col parts * 2^-56
            }
            float2 ar = unpack2(accr2);
            float accr = ar.x + ar.y;
#pragma unroll
            for (int o = 16; o > 0; o >>= 1) accr += __shfl_xor_sync(0xffffffffu, accr, o);
            if (lane == 0) s_r[i] = accr;                    // rowsum * 2^-56
        }
        u64* cp2 = (u64*)(s_cpart + w * SK_CP_STRIDE);
#pragma unroll
        for (int t = 0; t < 9; t++) cp2[lane + 32 * t] = pc[t];
        __syncthreads();

        if (tid < N1) s_alpha[tid] = MU_S / s_r[tid];        // = MU / rowsum (true alpha)
        if (tid < N2) {
            float sc = 0.f;
#pragma unroll
            for (int ww = 0; ww < SK_NW; ww++) sc += s_cpart[ww * SK_CP_STRIDE + tid];
            s_beta[tid] = NU_S / sc;                         // = NU / colsum (true beta)
        }
        __syncthreads();
    }

    for (int i = tid; i < N1; i += SK_THREADS) alpha_out[bh * N1 + i] = s_alpha[i];
    for (int j = tid; j < N2; j += SK_THREADS) beta_out[bh * N2 + j] = s_beta[j];
}

// ---------------------------------------------------------------------------
// ctx = (N1*N2 * sim * exp(20*sim-9) * alpha_n * beta_m) @ v
// (fp32 A recomputed with the SAME shift as Sinkhorn's -> consistent T.)
// ---------------------------------------------------------------------------
__global__ __launch_bounds__(256) void av_kernel(
    const float* __restrict__ sim_all, const float* __restrict__ v_all,
    const float* __restrict__ alpha, const float* __restrict__ beta,
    float* __restrict__ ctx)
{
    __shared__ __align__(16) float Ss[64][68];   // [m][n]
    __shared__ __align__(16) float Vs[64][68];   // [m][c]
    __shared__ float sa[64];
    __shared__ float sb[64];
    int bh = blockIdx.y;
    int n0 = blockIdx.x * 64;
    const float* simp = sim_all + (size_t)bh * N1 * N2;
    const float* vp   = v_all   + (size_t)bh * N2 * HD;
    int tid = threadIdx.x, tx = tid & 15, ty = tid >> 4;
    int lr = tid >> 2;

    if (tid < 64) sa[tid] = alpha[bh * N1 + n0 + tid] * 147456.0f;  // fold N1*N2

    u64 acc2[4][2];
#pragma unroll
    for (int i = 0; i < 4; i++) { acc2[i][0] = 0ull; acc2[i][1] = 0ull; }

    for (int m0 = 0; m0 < N2; m0 += 64) {
        if (tid < 64) sb[tid] = beta[bh * N2 + m0 + tid];
        __syncthreads();          // guards sa/sb visible + previous compute done
#pragma unroll
        for (int it = 0; it < 4; it++) {
            int lc = (((tid & 3) + (it << 2)) << 2);
            size_t idx = (size_t)(n0 + lr) * N2 + m0 + lc;
            float4 sv = *(const float4*)(simp + idx);
            float an = sa[lr];
            Ss[lc + 0][lr] = sv.x * __expf(fmaf(sv.x, 20.f, -9.f)) * an * sb[lc + 0];
            Ss[lc + 1][lr] = sv.y * __expf(fmaf(sv.y, 20.f, -9.f)) * an * sb[lc + 1];
            Ss[lc + 2][lr] = sv.z * __expf(fmaf(sv.z, 20.f, -9.f)) * an * sb[lc + 2];
            Ss[lc + 3][lr] = sv.w * __expf(fmaf(sv.w, 20.f, -9.f)) * an * sb[lc + 3];
            float4 vv = *(const float4*)(vp + (size_t)(m0 + lr) * HD + lc);
            *(float4*)&Vs[lr][lc] = vv;
        }
        __syncthreads();
#pragma unroll 8
        for (int kk = 0; kk < 64; kk++) {
            float4 a = *(const float4*)&Ss[kk][ty << 2];
            float4 b = *(const float4*)&Vs[kk][tx << 2];
            u64 b01 = pack2(b.x, b.y), b23 = pack2(b.z, b.w);
            float av[4] = {a.x, a.y, a.z, a.w};
#pragma unroll
            for (int i = 0; i < 4; i++) {
                u64 ad = pack2(av[i], av[i]);
                acc2[i][0] = ffma2(ad, b01, acc2[i][0]);
                acc2[i][1] = ffma2(ad, b23, acc2[i][1]);
            }
        }
    }
    int b = bh >> 3, h = bh & 7;
#pragma unroll
    for (int i = 0; i < 4; i++) {
        float2 p0 = unpack2(acc2[i][0]);
        float2 p1 = unpack2(acc2[i][1]);
        float* dst = ctx + (size_t)(b * N1 + n0 + (ty << 2) + i) * DIM + h * HD + (tx << 2);
        *(float4*)dst = make_float4(p0.x, p0.y, p1.x, p1.y);
    }
}

// ---------------------------------------------------------------------------
// In-place row L2 normalization (plain divide): rows of 512 floats
// ---------------------------------------------------------------------------
__global__ __launch_bounds__(128) void norm_rows_kernel(float* __restrict__ out)
{
    __shared__ float red[4];
    int row = blockIdx.x;
    float4* p = (float4*)(out + (size_t)row * DIM);
    int tid = threadIdx.x;
    float4 v = p[tid];
    float ss = v.x * v.x + v.y * v.y + v.z * v.z + v.w * v.w;
#pragma unroll
    for (int o = 16; o > 0; o >>= 1) ss += __shfl_xor_sync(0xffffffffu, ss, o);
    if ((tid & 31) == 0) red[tid >> 5] = ss;
    __syncthreads();
    float tot = red[0] + red[1] + red[2] + red[3];
    float inv = 1.0f / sqrtf(tot);
    v.x *= inv; v.y *= inv; v.z *= inv; v.w *= inv;
    p[tid] = v;
}

// ---------------------------------------------------------------------------
extern "C" void kernel_launch(void* const* d_in, const int* in_sizes, int n_in,
                              void* d_out, int out_size)
{
    (void)in_sizes; (void)n_in; (void)out_size;
    const float* F_t = (const float*)d_in[0];
    const float* F_s = (const float*)d_in[1];
    const float* Wq  = (const float*)d_in[2];
    const float* bq  = (const float*)d_in[3];
    const float* Wk  = (const float*)d_in[4];
    const float* bk  = (const float*)d_in[5];
    const float* Wv  = (const float*)d_in[6];
    const float* bv  = (const float*)d_in[7];
    const float* Wp  = (const float*)d_in[8];
    const float* bp  = (const float*)d_in[9];
    float* out = (float*)d_out;

    float *q, *k, *v, *simb, *alpha, *beta, *ctx;
    __half* A16;
    cudaGetSymbolAddress((void**)&q, g_q);
    cudaGetSymbolAddress((void**)&k, g_k);
    cudaGetSymbolAddress((void**)&v, g_v);
    cudaGetSymbolAddress((void**)&simb, g_sim);
    cudaGetSymbolAddress((void**)&A16, g_A16);
    cudaGetSymbolAddress((void**)&alpha, g_alpha);
    cudaGetSymbolAddress((void**)&beta, g_beta);
    cudaGetSymbolAddress((void**)&ctx, g_ctx);

    // allow ~79KB dynamic smem for the 32-warp sinkhorn (attribute set, not alloc)
    cudaFuncSetAttribute(sinkhorn_kernel,
                         cudaFuncAttributeMaxDynamicSharedMemorySize, SK_SMEM_BYTES);

    // 1) Q projection fused with transpose + per-head l2norm  -> g_q [B,H,N1,64]
    gemm128_kernel<1><<<dim3(DIM / 128, B * N1 / 128), 256>>>(
        F_t, Wq, nullptr, bq, nullptr, q, nullptr, B * N1, DIM, DIM);

    // 2) K+V fused projection (N=1024) with transpose (+norm for K)
    gemm128_kernel<2><<<dim3(1024 / 128, B * N2 / 128), 256>>>(
        F_s, Wk, Wv, bk, bv, k, v, B * N2, 1024, DIM);

    // 3) sim (fp32) + fp16 shifted Gibbs kernel A = exp(20*sim - 9)
    sim_kernel<<<dim3(N2 / 64, N1 / 64, BH), 256>>>(q, k, simb, A16);

    // 4) 100 Sinkhorn iterations, one 1024-thread CTA per (b,h)
    sinkhorn_kernel<<<BH, SK_THREADS, SK_SMEM_BYTES>>>(A16, alpha, beta);

    // 5) score @ v -> ctx [B*N1, 512]  (fp32 shifted A recomputed from sim)
    av_kernel<<<dim3(N1 / 64, BH), 256>>>(simb, v, alpha, beta, ctx);

    // 6) projection + 7) row normalize (in place in d_out)
    gemm128_kernel<0><<<dim3(DIM / 128, B * N1 / 128), 256>>>(
        ctx, Wp, nullptr, bp, nullptr, out, nullptr, B * N1, DIM, DIM);
    norm_rows_kernel<<<B * N1, 128>>>(out);
}

// round 12
// speedup vs baseline: 1.6494x; 1.0028x over previous
#include <cuda_runtime.h>
#include <cuda_fp16.h>
#include <math.h>

// Problem constants
constexpr int B   = 16;
constexpr int H   = 8;
constexpr int N1  = 256;
constexpr int N2  = 576;
constexpr int HD  = 64;
constexpr int DIM = 512;
constexpr int BH  = B * H;       // 128
constexpr int ITERS = 100;

typedef unsigned long long u64;
typedef unsigned int u32;

// ---- packed f32x2 helpers (sm_103a FFMA2; ptxas never auto-fuses) ----
__device__ __forceinline__ u64 ffma2(u64 a, u64 b, u64 c) {
    u64 d; asm("fma.rn.f32x2 %0,%1,%2,%3;" : "=l"(d) : "l"(a), "l"(b), "l"(c)); return d;
}
__device__ __forceinline__ u64 pack2(float x, float y) {
    u64 d; asm("mov.b64 %0,{%1,%2};" : "=l"(d) : "f"(x), "f"(y)); return d;
}
__device__ __forceinline__ float2 unpack2(u64 d) {
    float2 r; asm("mov.b64 {%0,%1},%2;" : "=f"(r.x), "=f"(r.y) : "l"(d)); return r;
}

// Static scratch (no runtime allocation allowed)
__device__ float g_q[BH * N1 * HD];
__device__ float g_k[BH * N2 * HD];
__device__ float g_v[BH * N2 * HD];
__device__ __half g_A16[(size_t)BH * N1 * N2];   // fp16 shifted Gibbs kernel e^(20 sim - 9)
__device__ __half g_P16[(size_t)BH * N1 * N2];   // fp16 sim * e^(20 sim - 9)  (for av)
__device__ float g_alpha[BH * N1];
__device__ float g_beta[BH * N2];
__device__ float g_ctx[B * N1 * DIM];

// ---------------------------------------------------------------------------
// fp32 GEMM, 128x128 tile, 256 threads, 8x8/thread, FFMA2 inner product.
// MODE 0: plain  out0[M,N] = X@W0^T + bias0
// MODE 1: q epilogue  — add bias, per-head (64-col quadrant) L2 norm,
//         scatter to [B,H,N1,64] layout in out0.
// MODE 2: kv epilogue — N=1024 logical; cols [0,512) from W0 (k, normalized,
//         -> out0), cols [512,1024) from W1 (v, raw -> out1), layout [B,H,N2,64].
// ---------------------------------------------------------------------------
template<int MODE>
__global__ __launch_bounds__(256) void gemm128_kernel(
    const float* __restrict__ X,
    const float* __restrict__ W0, const float* __restrict__ W1,
    const float* __restrict__ bias0, const float* __restrict__ bias1,
    float* __restrict__ out0, float* __restrict__ out1,
    int M, int N, int K)
{
    __shared__ __align__(16) float Xs[16][132];
    __shared__ __align__(16) float Ws[16][132];
    const int tid = threadIdx.x;
    const int tx = tid & 15, ty = tid >> 4;
    const int bm = blockIdx.y * 128, bn = blockIdx.x * 128;
    const int lr = tid >> 1;            // 0..127
    const int lc = (tid & 1) * 8;       // 0 or 8

    const float* Wsel;
    const float* bsel;
    if (MODE == 2 && bn >= 512) { Wsel = W1 + (size_t)(bn - 512) * K; bsel = bias1 + (bn - 512); }
    else                        { Wsel = W0 + (size_t)bn * K;         bsel = bias0 + bn; }

    u64 acc[2][2][4][2];
#pragma unroll
    for (int iq = 0; iq < 2; iq++)
#pragma unroll
        for (int jq = 0; jq < 2; jq++)
#pragma unroll
            for (int i = 0; i < 4; i++) { acc[iq][jq][i][0] = 0ull; acc[iq][jq][i][1] = 0ull; }

    const float* Xp = X + (size_t)(bm + lr) * K + lc;
    const float* Wp = Wsel + (size_t)lr * K + lc;

    for (int k0 = 0; k0 < K; k0 += 16) {
        float4 x0 = *(const float4*)(Xp + k0);
        float4 x1 = *(const float4*)(Xp + k0 + 4);
        float4 w0 = *(const float4*)(Wp + k0);
        float4 w1 = *(const float4*)(Wp + k0 + 4);
        Xs[lc + 0][lr] = x0.x; Xs[lc + 1][lr] = x0.y; Xs[lc + 2][lr] = x0.z; Xs[lc + 3][lr] = x0.w;
        Xs[lc + 4][lr] = x1.x; Xs[lc + 5][lr] = x1.y; Xs[lc + 6][lr] = x1.z; Xs[lc + 7][lr] = x1.w;
        Ws[lc + 0][lr] = w0.x; Ws[lc + 1][lr] = w0.y; Ws[lc + 2][lr] = w0.z; Ws[lc + 3][lr] = w0.w;
        Ws[lc + 4][lr] = w1.x; Ws[lc + 5][lr] = w1.y; Ws[lc + 6][lr] = w1.z; Ws[lc + 7][lr] = w1.w;
        __syncthreads();
#pragma unroll
        for (int kk = 0; kk < 16; kk++) {
            float4 a0 = *(const float4*)&Xs[kk][ty * 4];
            float4 a1 = *(const float4*)&Xs[kk][64 + ty * 4];
            float4 b0 = *(const float4*)&Ws[kk][tx * 4];
            float4 b1 = *(const float4*)&Ws[kk][64 + tx * 4];
            u64 bp[2][2] = {{pack2(b0.x, b0.y), pack2(b0.z, b0.w)},
                            {pack2(b1.x, b1.y), pack2(b1.z, b1.w)}};
            float av[2][4] = {{a0.x, a0.y, a0.z, a0.w}, {a1.x, a1.y, a1.z, a1.w}};
#pragma unroll
            for (int iq = 0; iq < 2; iq++)
#pragma unroll
                for (int i = 0; i < 4; i++) {
                    u64 ad = pack2(av[iq][i], av[iq][i]);
#pragma unroll
                    for (int jq = 0; jq < 2; jq++) {
                        acc[iq][jq][i][0] = ffma2(ad, bp[jq][0], acc[iq][jq][i][0]);
                        acc[iq][jq][i][1] = ffma2(ad, bp[jq][1], acc[iq][jq][i][1]);
                    }
                }
        }
        __syncthreads();
    }

    float4 bb0 = *(const float4*)(bsel + (tx << 2));
    float4 bb1 = *(const float4*)(bsel + 64 + (tx << 2));

    if (MODE == 0) {
#pragma unroll
        for (int iq = 0; iq < 2; iq++)
#pragma unroll
            for (int i = 0; i < 4; i++) {
                int r = bm + iq * 64 + ty * 4 + i;
#pragma unroll
                for (int jq = 0; jq < 2; jq++) {
                    int c = bn + jq * 64 + (tx << 2);
                    float4 bb = jq ? bb1 : bb0;
                    float2 p0 = unpack2(acc[iq][jq][i][0]);
                    float2 p1 = unpack2(acc[iq][jq][i][1]);
                    *(float4*)(out0 + (size_t)r * N + c) =
                        make_float4(p0.x + bb.x, p0.y + bb.y, p1.x + bb.z, p1.y + bb.w);
                }
            }
    } else {
        const bool do_norm = (MODE == 1) || (bn < 512);
#pragma unroll
        for (int iq = 0; iq < 2; iq++)
#pragma unroll
            for (int i = 0; i < 4; i++) {
                int r = bm + iq * 64 + ty * 4 + i;
                int b, nn;
                if (MODE == 1) { b = r >> 8; nn = r & 255; }
                else           { b = r / N2; nn = r - b * N2; }
#pragma unroll
                for (int jq = 0; jq < 2; jq++) {
                    float4 bb = jq ? bb1 : bb0;
                    float2 p0 = unpack2(acc[iq][jq][i][0]);
                    float2 p1 = unpack2(acc[iq][jq][i][1]);
                    float v0 = p0.x + bb.x, v1 = p0.y + bb.y;
                    float v2 = p1.x + bb.z, v3 = p1.y + bb.w;
                    float s = 1.f;
                    if (do_norm) {
                        float ss = v0 * v0 + v1 * v1 + v2 * v2 + v3 * v3;
                        ss += __shfl_xor_sync(0xffffffffu, ss, 1);
                        ss += __shfl_xor_sync(0xffffffffu, ss, 2);
                        ss += __shfl_xor_sync(0xffffffffu, ss, 4);
                        ss += __shfl_xor_sync(0xffffffffu, ss, 8);
                        s = 1.0f / fmaxf(sqrtf(ss), 1e-12f);
                    }
                    int c0 = bn + jq * 64;
                    float* dst;
                    if (MODE == 1) {
                        int h = c0 >> 6;
                        dst = out0 + ((size_t)((b * H + h) * N1 + nn)) * 64 + (tx << 2);
                    } else if (c0 < 512) {
                        int h = c0 >> 6;
                        dst = out0 + ((size_t)((b * H + h) * N2 + nn)) * 64 + (tx << 2);
                    } else {
                        int h = (c0 - 512) >> 6;
                        dst = out1 + ((size_t)((b * H + h) * N2 + nn)) * 64 + (tx << 2);
                    }
                    *(float4*)dst = make_float4(v0 * s, v1 * s, v2 * s, v3 * s);
                }
            }
    }
}

// ---------------------------------------------------------------------------
// sim = q.k (beta_t=1); store fp16 shifted A = exp(20*sim - 9) for Sinkhorn
// and fp16 P = sim * exp(20*sim - 9) for av (no fp32 sim array anymore).
// |P| <= e^11 ~ 6.07e4 < 65504 -> fp16 safe.
// ---------------------------------------------------------------------------
__global__ __launch_bounds__(256) void sim_kernel(
    const float* __restrict__ q, const float* __restrict__ k,
    __half* __restrict__ Ao, __half* __restrict__ Po)
{
    __shared__ __align__(16) float Qs[64][68];
    __shared__ __align__(16) float Ks[64][68];
    int bh = blockIdx.z;
    int i0 = blockIdx.y * 64, j0 = blockIdx.x * 64;
    const float* qp = q + (size_t)bh * N1 * HD;
    const float* kp = k + (size_t)bh * N2 * HD;
    int tid = threadIdx.x;
    int tx = tid & 15, ty = tid >> 4;
    int lr = tid >> 2;
#pragma unroll
    for (int it = 0; it < 4; it++) {
        int lc = (((tid & 3) + (it << 2)) << 2);
        float4 qv = *(const float4*)(qp + (size_t)(i0 + lr) * HD + lc);
        Qs[lc + 0][lr] = qv.x; Qs[lc + 1][lr] = qv.y; Qs[lc + 2][lr] = qv.z; Qs[lc + 3][lr] = qv.w;
        float4 kv = *(const float4*)(kp + (size_t)(j0 + lr) * HD + lc);
        Ks[lc + 0][lr] = kv.x; Ks[lc + 1][lr] = kv.y; Ks[lc + 2][lr] = kv.z; Ks[lc + 3][lr] = kv.w;
    }
    __syncthreads();
    u64 acc2[4][2];
#pragma unroll
    for (int i = 0; i < 4; i++) { acc2[i][0] = 0ull; acc2[i][1] = 0ull; }
#pragma unroll 8
    for (int kk = 0; kk < 64; kk++) {
        float4 a = *(const float4*)&Qs[kk][ty << 2];
        float4 b = *(const float4*)&Ks[kk][tx << 2];
        u64 b01 = pack2(b.x, b.y), b23 = pack2(b.z, b.w);
        float av[4] = {a.x, a.y, a.z, a.w};
#pragma unroll
        for (int i = 0; i < 4; i++) {
            u64 ad = pack2(av[i], av[i]);
            acc2[i][0] = ffma2(ad, b01, acc2[i][0]);
            acc2[i][1] = ffma2(ad, b23, acc2[i][1]);
        }
    }
    size_t base = (size_t)bh * N1 * N2;
#pragma unroll
    for (int i = 0; i < 4; i++) {
        size_t idx = base + (size_t)(i0 + (ty << 2) + i) * N2 + (j0 + (tx << 2));
        float2 p0 = unpack2(acc2[i][0]);
        float2 p1 = unpack2(acc2[i][1]);
        float e0 = __expf(fmaf(p0.x, 20.0f, -9.0f));
        float e1 = __expf(fmaf(p0.y, 20.0f, -9.0f));
        float e2 = __expf(fmaf(p1.x, 20.0f, -9.0f));
        float e3 = __expf(fmaf(p1.y, 20.0f, -9.0f));
        __half2* A2 = (__half2*)(Ao + idx);
        A2[0] = __floats2half2_rn(e0, e1);
        A2[1] = __floats2half2_rn(e2, e3);
        __half2* P2 = (__half2*)(Po + idx);
        P2[0] = __floats2half2_rn(p0.x * e0, p0.y * e1);
        P2[1] = __floats2half2_rn(p1.x * e2, p1.y * e3);
    }
}

// ---------------------------------------------------------------------------
// Sinkhorn, fp16 shifted A, ONE CTA of 1024 threads (32 warps) per bh slice.
// Proven structure (8 rows/warp, unroll 4 -> 36 loads in flight); fp16->f32x2
// via shift/mask bit trick (exact; 2^56 pre-scaling of alpha/beta compensates,
// folded into MU/NU).
// ---------------------------------------------------------------------------
constexpr int SK_THREADS = 1024;
constexpr int SK_NW = SK_THREADS / 32;          // 32 warps
constexpr int SK_RPW = N1 / SK_NW;              // 8 rows per warp
constexpr int SK_CP_STRIDE = 584;               // padded col-partial stride
constexpr int SK_OFF_ALPHA = 0;                 // [256]
constexpr int SK_OFF_R     = 256;               // [256]
constexpr int SK_OFF_BETA  = 512;               // [576] (8B aligned)
constexpr int SK_OFF_CP    = 1088;              // [32][584]
constexpr int SK_SMEM_FLOATS = SK_OFF_CP + SK_NW * SK_CP_STRIDE;
constexpr int SK_SMEM_BYTES  = SK_SMEM_FLOATS * 4;   // ~79KB

__global__ __launch_bounds__(SK_THREADS, 1) void sinkhorn_kernel(
    const __half* __restrict__ A16, float* __restrict__ alpha_out,
    float* __restrict__ beta_out)
{
    extern __shared__ __align__(16) float smem[];
    float* s_alpha = smem + SK_OFF_ALPHA;
    float* s_r     = smem + SK_OFF_R;
    float* s_beta  = smem + SK_OFF_BETA;
    float* s_cpart = smem + SK_OFF_CP;

    int bh = blockIdx.x;
    const u32* A = (const u32*)(A16 + (size_t)bh * N1 * N2);  // 288 u32 per row
    int tid = threadIdx.x, lane = tid & 31, w = tid >> 5;

    for (int i = tid; i < N1; i += SK_THREADS) s_alpha[i] = 1.f;
    for (int j = tid; j < N2; j += SK_THREADS) s_beta[j] = 1.f;
    __syncthreads();

    const float SC56  = 7.2057594037927936e16f;   // 2^56 (exact)
    const float MU_S  = (1.0f / 256.0f + 1e-8f) * 1.3877787807814457e-17f;  // MU * 2^-56
    const float NU_S  = (1.0f / 576.0f + 1e-8f) * 1.3877787807814457e-17f;  // NU * 2^-56
    const u64 C56 = pack2(SC56, SC56);
    const u64 ZERO2 = 0ull;

#pragma unroll 1
    for (int it = 0; it < ITERS; it++) {
        u64 pb[9], pc[9];
        const u64* sb2 = (const u64*)s_beta;
#pragma unroll
        for (int t = 0; t < 9; t++) {
            pb[t] = ffma2(sb2[lane + 32 * t], C56, ZERO2);   // beta * 2^56
            pc[t] = 0ull;
        }

#pragma unroll 4
        for (int rr = 0; rr < SK_RPW; rr++) {
            int i = w * SK_RPW + rr;
            float ais = s_alpha[i] * SC56;                   // alpha * 2^56
            u64 ad = pack2(ais, ais);
            u64 accr2 = 0ull;
            const u32* row = A + i * 288 + lane;
#pragma unroll
            for (int t = 0; t < 9; t++) {
                u32 x = row[32 * t];
                u32 lo = (x << 13) & 0x1fffe000u;            // h0 -> f32 bits * 2^-112
                u32 hi = (x >> 3)  & 0x1fffe000u;            // h1 -> f32 bits * 2^-112
                u64 a2 = ((u64)hi << 32) | (u64)lo;
                accr2 = ffma2(a2, pb[t], accr2);             // (A*2^-112)(b*2^56) = Ab*2^-56
                pc[t] = ffma2(a2, ad, pc[t]);                // col parts * 2^-56
            }
            float2 ar = unpack2(accr2);
            float accr = ar.x + ar.y;
#pragma unroll
            for (int o = 16; o > 0; o >>= 1) accr += __shfl_xor_sync(0xffffffffu, accr, o);
            if (lane == 0) s_r[i] = accr;                    // rowsum * 2^-56
        }
        u64* cp2 = (u64*)(s_cpart + w * SK_CP_STRIDE);
#pragma unroll
        for (int t = 0; t < 9; t++) cp2[lane + 32 * t] = pc[t];
        __syncthreads();

        if (tid < N1) s_alpha[tid] = MU_S / s_r[tid];        // = MU / rowsum (true alpha)
        if (tid < N2) {
            float sc = 0.f;
#pragma unroll
            for (int ww = 0; ww < SK_NW; ww++) sc += s_cpart[ww * SK_CP_STRIDE + tid];
            s_beta[tid] = NU_S / sc;                         // = NU / colsum (true beta)
        }
        __syncthreads();
    }

    for (int i = tid; i < N1; i += SK_THREADS) alpha_out[bh * N1 + i] = s_alpha[i];
    for (int j = tid; j < N2; j += SK_THREADS) beta_out[bh * N2 + j] = s_beta[j];
}

// ---------------------------------------------------------------------------
// ctx = (N1*N2 * P * alpha_n * beta_m) @ v, with P = fp16(sim * e^(20 sim-9))
// read directly (half the traffic of fp32 sim, no exp recompute).
// ---------------------------------------------------------------------------
__global__ __launch_bounds__(256) void av_kernel(
    const __half* __restrict__ P_all, const float* __restrict__ v_all,
    const float* __restrict__ alpha, const float* __restrict__ beta,
    float* __restrict__ ctx)
{
    __shared__ __align__(16) float Ss[64][68];   // [m][n]
    __shared__ __align__(16) float Vs[64][68];   // [m][c]
    __shared__ float sa[64];
    __shared__ float sb[64];
    int bh = blockIdx.y;
    int n0 = blockIdx.x * 64;
    const __half* Pp = P_all + (size_t)bh * N1 * N2;
    const float* vp  = v_all + (size_t)bh * N2 * HD;
    int tid = threadIdx.x, tx = tid & 15, ty = tid >> 4;
    int lr = tid >> 2;

    if (tid < 64) sa[tid] = alpha[bh * N1 + n0 + tid] * 147456.0f;  // fold N1*N2

    u64 acc2[4][2];
#pragma unroll
    for (int i = 0; i < 4; i++) { acc2[i][0] = 0ull; acc2[i][1] = 0ull; }

    for (int m0 = 0; m0 < N2; m0 += 64) {
        if (tid < 64) sb[tid] = beta[bh * N2 + m0 + tid];
        __syncthreads();          // guards sa/sb visible + previous compute done
#pragma unroll
        for (int it = 0; it < 4; it++) {
            int lc = (((tid & 3) + (it << 2)) << 2);
            size_t idx = (size_t)(n0 + lr) * N2 + m0 + lc;
            u64 ph = *(const u64*)(Pp + idx);                // 4 fp16 P values
            float2 f01 = __half22float2(*(const __half2*)&ph);
            u32 phh = (u32)(ph >> 32);
            float2 f23 = __half22float2(*(const __half2*)&phh);
            float an = sa[lr];
            Ss[lc + 0][lr] = f01.x * an * sb[lc + 0];
            Ss[lc + 1][lr] = f01.y * an * sb[lc + 1];
            Ss[lc + 2][lr] = f23.x * an * sb[lc + 2];
            Ss[lc + 3][lr] = f23.y * an * sb[lc + 3];
            float4 vv = *(const float4*)(vp + (size_t)(m0 + lr) * HD + lc);
            *(float4*)&Vs[lr][lc] = vv;
        }
        __syncthreads();
#pragma unroll 8
        for (int kk = 0; kk < 64; kk++) {
            float4 a = *(const float4*)&Ss[kk][ty << 2];
            float4 b = *(const float4*)&Vs[kk][tx << 2];
            u64 b01 = pack2(b.x, b.y), b23 = pack2(b.z, b.w);
            float av[4] = {a.x, a.y, a.z, a.w};
#pragma unroll
            for (int i = 0; i < 4; i++) {
                u64 ad = pack2(av[i], av[i]);
                acc2[i][0] = ffma2(ad, b01, acc2[i][0]);
                acc2[i][1] = ffma2(ad, b23, acc2[i][1]);
            }
        }
    }
    int b = bh >> 3, h = bh & 7;
#pragma unroll
    for (int i = 0; i < 4; i++) {
        float2 p0 = unpack2(acc2[i][0]);
        float2 p1 = unpack2(acc2[i][1]);
        float* dst = ctx + (size_t)(b * N1 + n0 + (ty << 2) + i) * DIM + h * HD + (tx << 2);
        *(float4*)dst = make_float4(p0.x, p0.y, p1.x, p1.y);
    }
}

// ---------------------------------------------------------------------------
// In-place row L2 normalization (plain divide): rows of 512 floats
// ---------------------------------------------------------------------------
__global__ __launch_bounds__(128) void norm_rows_kernel(float* __restrict__ out)
{
    __shared__ float red[4];
    int row = blockIdx.x;
    float4* p = (float4*)(out + (size_t)row * DIM);
    int tid = threadIdx.x;
    float4 v = p[tid];
    float ss = v.x * v.x + v.y * v.y + v.z * v.z + v.w * v.w;
#pragma unroll
    for (int o = 16; o > 0; o >>= 1) ss += __shfl_xor_sync(0xffffffffu, ss, o);
    if ((tid & 31) == 0) red[tid >> 5] = ss;
    __syncthreads();
    float tot = red[0] + red[1] + red[2] + red[3];
    float inv = 1.0f / sqrtf(tot);
    v.x *= inv; v.y *= inv; v.z *= inv; v.w *= inv;
    p[tid] = v;
}

// ---------------------------------------------------------------------------
extern "C" void kernel_launch(void* const* d_in, const int* in_sizes, int n_in,
                              void* d_out, int out_size)
{
    (void)in_sizes; (void)n_in; (void)out_size;
    const float* F_t = (const float*)d_in[0];
    const float* F_s = (const float*)d_in[1];
    const float* Wq  = (const float*)d_in[2];
    const float* bq  = (const float*)d_in[3];
    const float* Wk  = (const float*)d_in[4];
    const float* bk  = (const float*)d_in[5];
    const float* Wv  = (const float*)d_in[6];
    const float* bv  = (const float*)d_in[7];
    const float* Wp  = (const float*)d_in[8];
    const float* bp  = (const float*)d_in[9];
    float* out = (float*)d_out;

    float *q, *k, *v, *alpha, *beta, *ctx;
    __half *A16, *P16;
    cudaGetSymbolAddress((void**)&q, g_q);
    cudaGetSymbolAddress((void**)&k, g_k);
    cudaGetSymbolAddress((void**)&v, g_v);
    cudaGetSymbolAddress((void**)&A16, g_A16);
    cudaGetSymbolAddress((void**)&P16, g_P16);
    cudaGetSymbolAddress((void**)&alpha, g_alpha);
    cudaGetSymbolAddress((void**)&beta, g_beta);
    cudaGetSymbolAddress((void**)&ctx, g_ctx);

    // allow ~79KB dynamic smem for the 32-warp sinkhorn (attribute set, not alloc)
    cudaFuncSetAttribute(sinkhorn_kernel,
                         cudaFuncAttributeMaxDynamicSharedMemorySize, SK_SMEM_BYTES);

    // 1) Q projection fused with transpose + per-head l2norm  -> g_q [B,H,N1,64]
    gemm128_kernel<1><<<dim3(DIM / 128, B * N1 / 128), 256>>>(
        F_t, Wq, nullptr, bq, nullptr, q, nullptr, B * N1, DIM, DIM);

    // 2) K+V fused projection (N=1024) with transpose (+norm for K)
    gemm128_kernel<2><<<dim3(1024 / 128, B * N2 / 128), 256>>>(
        F_s, Wk, Wv, bk, bv, k, v, B * N2, 1024, DIM);

    // 3) sim -> fp16 A (Sinkhorn) + fp16 P (av); no fp32 sim array
    sim_kernel<<<dim3(N2 / 64, N1 / 64, BH), 256>>>(q, k, A16, P16);

    // 4) 100 Sinkhorn iterations, one 1024-thread CTA per (b,h)
    sinkhorn_kernel<<<BH, SK_THREADS, SK_SMEM_BYTES>>>(A16, alpha, beta);

    // 5) score @ v -> ctx [B*N1, 512]
    av_kernel<<<dim3(N1 / 64, BH), 256>>>(P16, v, alpha, beta, ctx);

    // 6) projection + 7) row normalize (in place in d_out)
    gemm128_kernel<0><<<dim3(DIM / 128, B * N1 / 128), 256>>>(
        ctx, Wp, nullptr, bp, nullptr, out, nullptr, B * N1, DIM, DIM);
    norm_rows_kernel<<<B * N1, 128>>>(out);
}

// round 13
// speedup vs baseline: 1.6807x; 1.0189x over previous
#include <cuda_runtime.h>
#include <cuda_fp16.h>
#include <math.h>

// Problem constants
constexpr int B   = 16;
constexpr int H   = 8;
constexpr int N1  = 256;
constexpr int N2  = 576;
constexpr int HD  = 64;
constexpr int DIM = 512;
constexpr int BH  = B * H;       // 128
constexpr int ITERS = 100;

typedef unsigned long long u64;
typedef unsigned int u32;

// ---- packed f32x2 helpers (sm_103a FFMA2; ptxas never auto-fuses) ----
__device__ __forceinline__ u64 ffma2(u64 a, u64 b, u64 c) {
    u64 d; asm("fma.rn.f32x2 %0,%1,%2,%3;" : "=l"(d) : "l"(a), "l"(b), "l"(c)); return d;
}
__device__ __forceinline__ u64 pack2(float x, float y) {
    u64 d; asm("mov.b64 %0,{%1,%2};" : "=l"(d) : "f"(x), "f"(y)); return d;
}
__device__ __forceinline__ float2 unpack2(u64 d) {
    float2 r; asm("mov.b64 {%0,%1},%2;" : "=f"(r.x), "=f"(r.y) : "l"(d)); return r;
}

// Static scratch (no runtime allocation allowed)
__device__ float g_q[BH * N1 * HD];
__device__ float g_k[BH * N2 * HD];
__device__ float g_v[BH * N2 * HD];
__device__ __half g_A16[(size_t)BH * N1 * N2];   // fp16 shifted Gibbs kernel e^(20 sim - 9)
__device__ __half g_P16[(size_t)BH * N1 * N2];   // fp16 sim * e^(20 sim - 9)  (for av)
__device__ float g_alpha[BH * N1];
__device__ float g_beta[BH * N2];
__device__ float g_ctx[B * N1 * DIM];

// ---------------------------------------------------------------------------
// fp32 GEMM, 128x128 tile, 256 threads, 8x8/thread, FFMA2 inner product.
// MODE 0: plain  out0[M,N] = X@W0^T + bias0   (grid (N/128, M/128))
// MODE 3: fused QKV. grid (8, 104):
//   by <  72 : KV CTA. rows = F_s row block by (9216 rows), cols: bn<512 -> K
//              (W0/b0, normalized, out0 [B,H,N2,64]); bn>=512 -> V (W1/b1,
//              raw, out1 [B,H,N2,64]).
//   by >= 72 : Q CTA (bx<4 only). rows = F_t row block by-72 (4096 rows),
//              W2/b2, normalized, out2 [B,H,N1,64].
// ---------------------------------------------------------------------------
template<int MODE>
__global__ __launch_bounds__(256) void gemm128_kernel(
    const float* __restrict__ X,  const float* __restrict__ X2,
    const float* __restrict__ W0, const float* __restrict__ W1,
    const float* __restrict__ W2,
    const float* __restrict__ bias0, const float* __restrict__ bias1,
    const float* __restrict__ bias2,
    float* __restrict__ out0, float* __restrict__ out1,
    float* __restrict__ out2,
    int M, int N, int K)
{
    const int bx = blockIdx.x, by = blockIdx.y;
    bool isQ = false;
    int bm, bn = bx * 128;
    if (MODE == 3) {
        isQ = (by >= 72);
        if (isQ && bx >= 4) return;      // Q only spans 512 cols
        bm = isQ ? (by - 72) * 128 : by * 128;
    } else {
        bm = by * 128;
    }

    __shared__ __align__(16) float Xs[16][132];
    __shared__ __align__(16) float Ws[16][132];
    const int tid = threadIdx.x;
    const int tx = tid & 15, ty = tid >> 4;
    const int lr = tid >> 1;            // 0..127
    const int lc = (tid & 1) * 8;       // 0 or 8

    const float* Xbase = (MODE == 3 && isQ) ? X2 : X;
    const float* Wsel;
    const float* bsel;
    if (MODE == 3 && isQ)            { Wsel = W2 + (size_t)bn * K;         bsel = bias2 + bn; }
    else if (MODE == 3 && bn >= 512) { Wsel = W1 + (size_t)(bn - 512) * K; bsel = bias1 + (bn - 512); }
    else                             { Wsel = W0 + (size_t)bn * K;         bsel = bias0 + bn; }

    u64 acc[2][2][4][2];
#pragma unroll
    for (int iq = 0; iq < 2; iq++)
#pragma unroll
        for (int jq = 0; jq < 2; jq++)
#pragma unroll
            for (int i = 0; i < 4; i++) { acc[iq][jq][i][0] = 0ull; acc[iq][jq][i][1] = 0ull; }

    const float* Xp = Xbase + (size_t)(bm + lr) * K + lc;
    const float* Wp = Wsel + (size_t)lr * K + lc;

    for (int k0 = 0; k0 < K; k0 += 16) {
        float4 x0 = *(const float4*)(Xp + k0);
        float4 x1 = *(const float4*)(Xp + k0 + 4);
        float4 w0 = *(const float4*)(Wp + k0);
        float4 w1 = *(const float4*)(Wp + k0 + 4);
        Xs[lc + 0][lr] = x0.x; Xs[lc + 1][lr] = x0.y; Xs[lc + 2][lr] = x0.z; Xs[lc + 3][lr] = x0.w;
        Xs[lc + 4][lr] = x1.x; Xs[lc + 5][lr] = x1.y; Xs[lc + 6][lr] = x1.z; Xs[lc + 7][lr] = x1.w;
        Ws[lc + 0][lr] = w0.x; Ws[lc + 1][lr] = w0.y; Ws[lc + 2][lr] = w0.z; Ws[lc + 3][lr] = w0.w;
        Ws[lc + 4][lr] = w1.x; Ws[lc + 5][lr] = w1.y; Ws[lc + 6][lr] = w1.z; Ws[lc + 7][lr] = w1.w;
        __syncthreads();
#pragma unroll
        for (int kk = 0; kk < 16; kk++) {
            float4 a0 = *(const float4*)&Xs[kk][ty * 4];
            float4 a1 = *(const float4*)&Xs[kk][64 + ty * 4];
            float4 b0 = *(const float4*)&Ws[kk][tx * 4];
            float4 b1 = *(const float4*)&Ws[kk][64 + tx * 4];
            u64 bp[2][2] = {{pack2(b0.x, b0.y), pack2(b0.z, b0.w)},
                            {pack2(b1.x, b1.y), pack2(b1.z, b1.w)}};
            float av[2][4] = {{a0.x, a0.y, a0.z, a0.w}, {a1.x, a1.y, a1.z, a1.w}};
#pragma unroll
            for (int iq = 0; iq < 2; iq++)
#pragma unroll
                for (int i = 0; i < 4; i++) {
                    u64 ad = pack2(av[iq][i], av[iq][i]);
#pragma unroll
                    for (int jq = 0; jq < 2; jq++) {
                        acc[iq][jq][i][0] = ffma2(ad, bp[jq][0], acc[iq][jq][i][0]);
                        acc[iq][jq][i][1] = ffma2(ad, bp[jq][1], acc[iq][jq][i][1]);
                    }
                }
        }
        __syncthreads();
    }

    float4 bb0 = *(const float4*)(bsel + (tx << 2));
    float4 bb1 = *(const float4*)(bsel + 64 + (tx << 2));

    if (MODE == 0) {
#pragma unroll
        for (int iq = 0; iq < 2; iq++)
#pragma unroll
            for (int i = 0; i < 4; i++) {
                int r = bm + iq * 64 + ty * 4 + i;
#pragma unroll
                for (int jq = 0; jq < 2; jq++) {
                    int c = bn + jq * 64 + (tx << 2);
                    float4 bb = jq ? bb1 : bb0;
                    float2 p0 = unpack2(acc[iq][jq][i][0]);
                    float2 p1 = unpack2(acc[iq][jq][i][1]);
                    *(float4*)(out0 + (size_t)r * N + c) =
                        make_float4(p0.x + bb.x, p0.y + bb.y, p1.x + bb.z, p1.y + bb.w);
                }
            }
    } else {
        const bool do_norm = isQ || (bn < 512);
#pragma unroll
        for (int iq = 0; iq < 2; iq++)
#pragma unroll
            for (int i = 0; i < 4; i++) {
                int r = bm + iq * 64 + ty * 4 + i;
                int b, nn;
                if (isQ) { b = r >> 8; nn = r & 255; }
                else     { b = r / N2; nn = r - b * N2; }
#pragma unroll
                for (int jq = 0; jq < 2; jq++) {
                    float4 bb = jq ? bb1 : bb0;
                    float2 p0 = unpack2(acc[iq][jq][i][0]);
                    float2 p1 = unpack2(acc[iq][jq][i][1]);
                    float v0 = p0.x + bb.x, v1 = p0.y + bb.y;
                    float v2 = p1.x + bb.z, v3 = p1.y + bb.w;
                    float s = 1.f;
                    if (do_norm) {
                        float ss = v0 * v0 + v1 * v1 + v2 * v2 + v3 * v3;
                        ss += __shfl_xor_sync(0xffffffffu, ss, 1);
                        ss += __shfl_xor_sync(0xffffffffu, ss, 2);
                        ss += __shfl_xor_sync(0xffffffffu, ss, 4);
                        ss += __shfl_xor_sync(0xffffffffu, ss, 8);
                        s = 1.0f / fmaxf(sqrtf(ss), 1e-12f);
                    }
                    int c0 = bn + jq * 64;
                    float* dst;
                    if (isQ) {
                        int h = c0 >> 6;
                        dst = out2 + ((size_t)((b * H + h) * N1 + nn)) * 64 + (tx << 2);
                    } else if (c0 < 512) {
                        int h = c0 >> 6;
                        dst = out0 + ((size_t)((b * H + h) * N2 + nn)) * 64 + (tx << 2);
                    } else {
                        int h = (c0 - 512) >> 6;
                        dst = out1 + ((size_t)((b * H + h) * N2 + nn)) * 64 + (tx << 2);
                    }
                    *(float4*)dst = make_float4(v0 * s, v1 * s, v2 * s, v3 * s);
                }
            }
    }
}

// ---------------------------------------------------------------------------
// sim = q.k (beta_t=1); store fp16 A = exp(20*sim-9) and fp16 P = sim*A.
// Retiled 128(i) x 64(j), 256 threads, 8x4 per thread (gemm128 ratio).
// Dynamic smem: Qs[64][132] + Ks[64][68] = ~51KB.
// ---------------------------------------------------------------------------
constexpr int SIM_SMEM_BYTES = (64 * 132 + 64 * 68) * 4;

__global__ __launch_bounds__(256) void sim_kernel(
    const float* __restrict__ q, const float* __restrict__ k,
    __half* __restrict__ Ao, __half* __restrict__ Po)
{
    extern __shared__ __align__(16) float ssm[];
    float (*Qs)[132] = (float(*)[132])ssm;            // [kk][i] 64x132
    float (*Ks)[68]  = (float(*)[68])(ssm + 64 * 132); // [kk][j] 64x68

    int bh = blockIdx.z;
    int i0 = blockIdx.y * 128, j0 = blockIdx.x * 64;
    const float* qp = q + (size_t)bh * N1 * HD;
    const float* kp = k + (size_t)bh * N2 * HD;
    int tid = threadIdx.x;
    int tx = tid & 15, ty = tid >> 4;

    // load Q tile: 128 rows x 64 cols; 2 threads per row, 8 float4 each
    {
        int lr = tid >> 1;
        int c8 = (tid & 1) * 8;
#pragma unroll
        for (int it = 0; it < 8; it++) {
            int lc = (c8 + it) * 4;
            float4 qv = *(const float4*)(qp + (size_t)(i0 + lr) * HD + lc);
            Qs[lc + 0][lr] = qv.x; Qs[lc + 1][lr] = qv.y;
            Qs[lc + 2][lr] = qv.z; Qs[lc + 3][lr] = qv.w;
        }
    }
    // load K tile: 64 rows x 64 cols; 4 threads per row, 4 float4 each
    {
        int lr = tid >> 2;
#pragma unroll
        for (int it = 0; it < 4; it++) {
            int lc = (((tid & 3) + (it << 2)) << 2);
            float4 kv = *(const float4*)(kp + (size_t)(j0 + lr) * HD + lc);
            Ks[lc + 0][lr] = kv.x; Ks[lc + 1][lr] = kv.y;
            Ks[lc + 2][lr] = kv.z; Ks[lc + 3][lr] = kv.w;
        }
    }
    __syncthreads();

    u64 acc2[2][4][2];
#pragma unroll
    for (int iq = 0; iq < 2; iq++)
#pragma unroll
        for (int i = 0; i < 4; i++) { acc2[iq][i][0] = 0ull; acc2[iq][i][1] = 0ull; }

#pragma unroll 8
    for (int kk = 0; kk < 64; kk++) {
        float4 a0 = *(const float4*)&Qs[kk][ty << 2];
        float4 a1 = *(const float4*)&Qs[kk][64 + (ty << 2)];
        float4 b  = *(const float4*)&Ks[kk][tx << 2];
        u64 b01 = pack2(b.x, b.y), b23 = pack2(b.z, b.w);
        float av[2][4] = {{a0.x, a0.y, a0.z, a0.w}, {a1.x, a1.y, a1.z, a1.w}};
#pragma unroll
        for (int iq = 0; iq < 2; iq++)
#pragma unroll
            for (int i = 0; i < 4; i++) {
                u64 ad = pack2(av[iq][i], av[iq][i]);
                acc2[iq][i][0] = ffma2(ad, b01, acc2[iq][i][0]);
                acc2[iq][i][1] = ffma2(ad, b23, acc2[iq][i][1]);
            }
    }
    size_t base = (size_t)bh * N1 * N2;
#pragma unroll
    for (int iq = 0; iq < 2; iq++)
#pragma unroll
        for (int i = 0; i < 4; i++) {
            int row = i0 + iq * 64 + (ty << 2) + i;
            size_t idx = base + (size_t)row * N2 + (j0 + (tx << 2));
            float2 p0 = unpack2(acc2[iq][i][0]);
            float2 p1 = unpack2(acc2[iq][i][1]);
            float e0 = __expf(fmaf(p0.x, 20.0f, -9.0f));
            float e1 = __expf(fmaf(p0.y, 20.0f, -9.0f));
            float e2 = __expf(fmaf(p1.x, 20.0f, -9.0f));
            float e3 = __expf(fmaf(p1.y, 20.0f, -9.0f));
            __half2* A2 = (__half2*)(Ao + idx);
            A2[0] = __floats2half2_rn(e0, e1);
            A2[1] = __floats2half2_rn(e2, e3);
            __half2* P2 = (__half2*)(Po + idx);
            P2[0] = __floats2half2_rn(p0.x * e0, p0.y * e1);
            P2[1] = __floats2half2_rn(p1.x * e2, p1.y * e3);
        }
}

// ---------------------------------------------------------------------------
// Sinkhorn, fp16 shifted A, ONE CTA of 1024 threads (32 warps) per bh slice.
// Proven structure (8 rows/warp, unroll 4 -> 36 loads in flight); fp16->f32x2
// via shift/mask bit trick (exact; 2^56 pre-scaling of alpha/beta compensates,
// folded into MU/NU).
// ---------------------------------------------------------------------------
constexpr int SK_THREADS = 1024;
constexpr int SK_NW = SK_THREADS / 32;          // 32 warps
constexpr int SK_RPW = N1 / SK_NW;              // 8 rows per warp
constexpr int SK_CP_STRIDE = 584;               // padded col-partial stride
constexpr int SK_OFF_ALPHA = 0;                 // [256]
constexpr int SK_OFF_R     = 256;               // [256]
constexpr int SK_OFF_BETA  = 512;               // [576] (8B aligned)
constexpr int SK_OFF_CP    = 1088;              // [32][584]
constexpr int SK_SMEM_FLOATS = SK_OFF_CP + SK_NW * SK_CP_STRIDE;
constexpr int SK_SMEM_BYTES  = SK_SMEM_FLOATS * 4;   // ~79KB

__global__ __launch_bounds__(SK_THREADS, 1) void sinkhorn_kernel(
    const __half* __restrict__ A16, float* __restrict__ alpha_out,
    float* __restrict__ beta_out)
{
    extern __shared__ __align__(16) float smem[];
    float* s_alpha = smem + SK_OFF_ALPHA;
    float* s_r     = smem + SK_OFF_R;
    float* s_beta  = smem + SK_OFF_BETA;
    float* s_cpart = smem + SK_OFF_CP;

    int bh = blockIdx.x;
    const u32* A = (const u32*)(A16 + (size_t)bh * N1 * N2);  // 288 u32 per row
    int tid = threadIdx.x, lane = tid & 31, w = tid >> 5;

    for (int i = tid; i < N1; i += SK_THREADS) s_alpha[i] = 1.f;
    for (int j = tid; j < N2; j += SK_THREADS) s_beta[j] = 1.f;
    __syncthreads();

    const float SC56  = 7.2057594037927936e16f;   // 2^56 (exact)
    const float MU_S  = (1.0f / 256.0f + 1e-8f) * 1.3877787807814457e-17f;  // MU * 2^-56
    const float NU_S  = (1.0f / 576.0f + 1e-8f) * 1.3877787807814457e-17f;  // NU * 2^-56
    const u64 C56 = pack2(SC56, SC56);
    const u64 ZERO2 = 0ull;

#pragma unroll 1
    for (int it = 0; it < ITERS; it++) {
        u64 pb[9], pc[9];
        const u64* sb2 = (const u64*)s_beta;
#pragma unroll
        for (int t = 0; t < 9; t++) {
            pb[t] = ffma2(sb2[lane + 32 * t], C56, ZERO2);   // beta * 2^56
            pc[t] = 0ull;
        }

#pragma unroll 4
        for (int rr = 0; rr < SK_RPW; rr++) {
            int i = w * SK_RPW + rr;
            float ais = s_alpha[i] * SC56;                   // alpha * 2^56
            u64 ad = pack2(ais, ais);
            u64 accr2 = 0ull;
            const u32* row = A + i * 288 + lane;
#pragma unroll
            for (int t = 0; t < 9; t++) {
                u32 x = row[32 * t];
                u32 lo = (x << 13) & 0x1fffe000u;            // h0 -> f32 bits * 2^-112
                u32 hi = (x >> 3)  & 0x1fffe000u;            // h1 -> f32 bits * 2^-112
                u64 a2 = ((u64)hi << 32) | (u64)lo;
                accr2 = ffma2(a2, pb[t], accr2);             // (A*2^-112)(b*2^56) = Ab*2^-56
                pc[t] = ffma2(a2, ad, pc[t]);                // col parts * 2^-56
            }
            float2 ar = unpack2(accr2);
            float accr = ar.x + ar.y;
#pragma unroll
            for (int o = 16; o > 0; o >>= 1) accr += __shfl_xor_sync(0xffffffffu, accr, o);
            if (lane == 0) s_r[i] = accr;                    // rowsum * 2^-56
        }
        u64* cp2 = (u64*)(s_cpart + w * SK_CP_STRIDE);
#pragma unroll
        for (int t = 0; t < 9; t++) cp2[lane + 32 * t] = pc[t];
        __syncthreads();

        if (tid < N1) s_alpha[tid] = MU_S / s_r[tid];        // = MU / rowsum (true alpha)
        if (tid < N2) {
            float sc = 0.f;
#pragma unroll
            for (int ww = 0; ww < SK_NW; ww++) sc += s_cpart[ww * SK_CP_STRIDE + tid];
            s_beta[tid] = NU_S / sc;                         // = NU / colsum (true beta)
        }
        __syncthreads();
    }

    for (int i = tid; i < N1; i += SK_THREADS) alpha_out[bh * N1 + i] = s_alpha[i];
    for (int j = tid; j < N2; j += SK_THREADS) beta_out[bh * N2 + j] = s_beta[j];
}

// ---------------------------------------------------------------------------
// ctx = (N1*N2 * P * alpha_n * beta_m) @ v, with P = fp16(sim * e^(20 sim-9))
// ---------------------------------------------------------------------------
__global__ __launch_bounds__(256) void av_kernel(
    const __half* __restrict__ P_all, const float* __restrict__ v_all,
    const float* __restrict__ alpha, const float* __restrict__ beta,
    float* __restrict__ ctx)
{
    __shared__ __align__(16) float Ss[64][68];   // [m][n]
    __shared__ __align__(16) float Vs[64][68];   // [m][c]
    __shared__ float sa[64];
    __shared__ float sb[64];
    int bh = blockIdx.y;
    int n0 = blockIdx.x * 64;
    const __half* Pp = P_all + (size_t)bh * N1 * N2;
    const float* vp  = v_all + (size_t)bh * N2 * HD;
    int tid = threadIdx.x, tx = tid & 15, ty = tid >> 4;
    int lr = tid >> 2;

    if (tid < 64) sa[tid] = alpha[bh * N1 + n0 + tid] * 147456.0f;  // fold N1*N2

    u64 acc2[4][2];
#pragma unroll
    for (int i = 0; i < 4; i++) { acc2[i][0] = 0ull; acc2[i][1] = 0ull; }

    for (int m0 = 0; m0 < N2; m0 += 64) {
        if (tid < 64) sb[tid] = beta[bh * N2 + m0 + tid];
        __syncthreads();          // guards sa/sb visible + previous compute done
#pragma unroll
        for (int it = 0; it < 4; it++) {
            int lc = (((tid & 3) + (it << 2)) << 2);
            size_t idx = (size_t)(n0 + lr) * N2 + m0 + lc;
            u64 ph = *(const u64*)(Pp + idx);                // 4 fp16 P values
            float2 f01 = __half22float2(*(const __half2*)&ph);
            u32 phh = (u32)(ph >> 32);
            float2 f23 = __half22float2(*(const __half2*)&phh);
            float an = sa[lr];
            Ss[lc + 0][lr] = f01.x * an * sb[lc + 0];
            Ss[lc + 1][lr] = f01.y * an * sb[lc + 1];
            Ss[lc + 2][lr] = f23.x * an * sb[lc + 2];
            Ss[lc + 3][lr] = f23.y * an * sb[lc + 3];
            float4 vv = *(const float4*)(vp + (size_t)(m0 + lr) * HD + lc);
            *(float4*)&Vs[lr][lc] = vv;
        }
        __syncthreads();
#pragma unroll 8
        for (int kk = 0; kk < 64; kk++) {
            float4 a = *(const float4*)&Ss[kk][ty << 2];
            float4 b = *(const float4*)&Vs[kk][tx << 2];
            u64 b01 = pack2(b.x, b.y), b23 = pack2(b.z, b.w);
            float av[4] = {a.x, a.y, a.z, a.w};
#pragma unroll
            for (int i = 0; i < 4; i++) {
                u64 ad = pack2(av[i], av[i]);
                acc2[i][0] = ffma2(ad, b01, acc2[i][0]);
                acc2[i][1] = ffma2(ad, b23, acc2[i][1]);
            }
        }
    }
    int b = bh >> 3, h = bh & 7;
#pragma unroll
    for (int i = 0; i < 4; i++) {
        float2 p0 = unpack2(acc2[i][0]);
        float2 p1 = unpack2(acc2[i][1]);
        float* dst = ctx + (size_t)(b * N1 + n0 + (ty << 2) + i) * DIM + h * HD + (tx << 2);
        *(float4*)dst = make_float4(p0.x, p0.y, p1.x, p1.y);
    }
}

// ---------------------------------------------------------------------------
// In-place row L2 normalization (plain divide): rows of 512 floats
// ---------------------------------------------------------------------------
__global__ __launch_bounds__(128) void norm_rows_kernel(float* __restrict__ out)
{
    __shared__ float red[4];
    int row = blockIdx.x;
    float4* p = (float4*)(out + (size_t)row * DIM);
    int tid = threadIdx.x;
    float4 v = p[tid];
    float ss = v.x * v.x + v.y * v.y + v.z * v.z + v.w * v.w;
#pragma unroll
    for (int o = 16; o > 0; o >>= 1) ss += __shfl_xor_sync(0xffffffffu, ss, o);
    if ((tid & 31) == 0) red[tid >> 5] = ss;
    __syncthreads();
    float tot = red[0] + red[1] + red[2] + red[3];
    float inv = 1.0f / sqrtf(tot);
    v.x *= inv; v.y *= inv; v.z *= inv; v.w *= inv;
    p[tid] = v;
}

// ---------------------------------------------------------------------------
extern "C" void kernel_launch(void* const* d_in, const int* in_sizes, int n_in,
                              void* d_out, int out_size)
{
    (void)in_sizes; (void)n_in; (void)out_size;
    const float* F_t = (const float*)d_in[0];
    const float* F_s = (const float*)d_in[1];
    const float* Wq  = (const float*)d_in[2];
    const float* bq  = (const float*)d_in[3];
    const float* Wk  = (const float*)d_in[4];
    const float* bk  = (const float*)d_in[5];
    const float* Wv  = (const float*)d_in[6];
    const float* bv  = (const float*)d_in[7];
    const float* Wp  = (const float*)d_in[8];
    const float* bp  = (const float*)d_in[9];
    float* out = (float*)d_out;

    float *q, *k, *v, *alpha, *beta, *ctx;
    __half *A16, *P16;
    cudaGetSymbolAddress((void**)&q, g_q);
    cudaGetSymbolAddress((void**)&k, g_k);
    cudaGetSymbolAddress((void**)&v, g_v);
    cudaGetSymbolAddress((void**)&A16, g_A16);
    cudaGetSymbolAddress((void**)&P16, g_P16);
    cudaGetSymbolAddress((void**)&alpha, g_alpha);
    cudaGetSymbolAddress((void**)&beta, g_beta);
    cudaGetSymbolAddress((void**)&ctx, g_ctx);

    // dynamic smem attributes (host API, capture-safe; proven since R7)
    cudaFuncSetAttribute(sinkhorn_kernel,
                         cudaFuncAttributeMaxDynamicSharedMemorySize, SK_SMEM_BYTES);
    cudaFuncSetAttribute(sim_kernel,
                         cudaFuncAttributeMaxDynamicSharedMemorySize, SIM_SMEM_BYTES);

    // 1+2) fused QKV projections (+ transpose, + l2norm for q,k) in ONE launch
    gemm128_kernel<3><<<dim3(8, 104), 256>>>(
        F_s, F_t, Wk, Wv, Wq, bk, bv, bq, k, v, q, 0, 0, DIM);

    // 3) sim -> fp16 A (Sinkhorn) + fp16 P (av); 128x64 tiles
    sim_kernel<<<dim3(N2 / 64, N1 / 128, BH), 256, SIM_SMEM_BYTES>>>(q, k, A16, P16);

    // 4) 100 Sinkhorn iterations, one 1024-thread CTA per (b,h)
    sinkhorn_kernel<<<BH, SK_THREADS, SK_SMEM_BYTES>>>(A16, alpha, beta);

    // 5) score @ v -> ctx [B*N1, 512]
    av_kernel<<<dim3(N1 / 64, BH), 256>>>(P16, v, alpha, beta, ctx);

    // 6) projection + 7) row normalize (in place in d_out)
    gemm128_kernel<0><<<dim3(DIM / 128, B * N1 / 128), 256>>>(
        ctx, nullptr, Wp, nullptr, nullptr, bp, nullptr, nullptr,
        out, nullptr, nullptr, B * N1, DIM, DIM);
    norm_rows_kernel<<<B * N1, 128>>>(out);
}

// round 14
// speedup vs baseline: 1.6922x; 1.0069x over previous
#include <cuda_runtime.h>
#include <cuda_fp16.h>
#include <math.h>

// Problem constants
constexpr int B   = 16;
constexpr int H   = 8;
constexpr int N1  = 256;
constexpr int N2  = 576;
constexpr int HD  = 64;
constexpr int DIM = 512;
constexpr int BH  = B * H;       // 128
constexpr int ITERS = 100;

typedef unsigned long long u64;
typedef unsigned int u32;

// ---- packed f32x2 helpers (sm_103a FFMA2; ptxas never auto-fuses) ----
__device__ __forceinline__ u64 ffma2(u64 a, u64 b, u64 c) {
    u64 d; asm("fma.rn.f32x2 %0,%1,%2,%3;" : "=l"(d) : "l"(a), "l"(b), "l"(c)); return d;
}
__device__ __forceinline__ u64 pack2(float x, float y) {
    u64 d; asm("mov.b64 %0,{%1,%2};" : "=l"(d) : "f"(x), "f"(y)); return d;
}
__device__ __forceinline__ float2 unpack2(u64 d) {
    float2 r; asm("mov.b64 {%0,%1},%2;" : "=f"(r.x), "=f"(r.y) : "l"(d)); return r;
}

// Static scratch (no runtime allocation allowed)
__device__ float g_q[BH * N1 * HD];
__device__ float g_k[BH * N2 * HD];
__device__ float g_v[BH * N2 * HD];
__device__ __half g_A16[(size_t)BH * N1 * N2];   // fp16 shifted Gibbs kernel e^(20 sim - 9)
__device__ __half g_P16[(size_t)BH * N1 * N2];   // fp16 sim * e^(20 sim - 9)  (for av)
__device__ float g_alpha[BH * N1];
__device__ float g_beta[BH * N2];
__device__ float g_ctx[B * N1 * DIM];

// ---------------------------------------------------------------------------
// fp32 GEMM, 128x128 tile, 256 threads, 8x8/thread, FFMA2 inner product.
// MODE 0: plain  out0[M,N] = X@W0^T + bias0   (grid (N/128, M/128))
// MODE 3: fused QKV. grid (8, 104):
//   by <  72 : KV CTA (F_s rows); bn<512 -> K (norm, out0), else V (out1).
//   by >= 72 : Q CTA (bx<4, F_t rows), norm, out2.
// ---------------------------------------------------------------------------
template<int MODE>
__global__ __launch_bounds__(256) void gemm128_kernel(
    const float* __restrict__ X,  const float* __restrict__ X2,
    const float* __restrict__ W0, const float* __restrict__ W1,
    const float* __restrict__ W2,
    const float* __restrict__ bias0, const float* __restrict__ bias1,
    const float* __restrict__ bias2,
    float* __restrict__ out0, float* __restrict__ out1,
    float* __restrict__ out2,
    int M, int N, int K)
{
    const int bx = blockIdx.x, by = blockIdx.y;
    bool isQ = false;
    int bm, bn = bx * 128;
    if (MODE == 3) {
        isQ = (by >= 72);
        if (isQ && bx >= 4) return;      // Q only spans 512 cols
        bm = isQ ? (by - 72) * 128 : by * 128;
    } else {
        bm = by * 128;
    }

    __shared__ __align__(16) float Xs[16][132];
    __shared__ __align__(16) float Ws[16][132];
    const int tid = threadIdx.x;
    const int tx = tid & 15, ty = tid >> 4;
    const int lr = tid >> 1;            // 0..127
    const int lc = (tid & 1) * 8;       // 0 or 8

    const float* Xbase = (MODE == 3 && isQ) ? X2 : X;
    const float* Wsel;
    const float* bsel;
    if (MODE == 3 && isQ)            { Wsel = W2 + (size_t)bn * K;         bsel = bias2 + bn; }
    else if (MODE == 3 && bn >= 512) { Wsel = W1 + (size_t)(bn - 512) * K; bsel = bias1 + (bn - 512); }
    else                             { Wsel = W0 + (size_t)bn * K;         bsel = bias0 + bn; }

    u64 acc[2][2][4][2];
#pragma unroll
    for (int iq = 0; iq < 2; iq++)
#pragma unroll
        for (int jq = 0; jq < 2; jq++)
#pragma unroll
            for (int i = 0; i < 4; i++) { acc[iq][jq][i][0] = 0ull; acc[iq][jq][i][1] = 0ull; }

    const float* Xp = Xbase + (size_t)(bm + lr) * K + lc;
    const float* Wp = Wsel + (size_t)lr * K + lc;

    for (int k0 = 0; k0 < K; k0 += 16) {
        float4 x0 = *(const float4*)(Xp + k0);
        float4 x1 = *(const float4*)(Xp + k0 + 4);
        float4 w0 = *(const float4*)(Wp + k0);
        float4 w1 = *(const float4*)(Wp + k0 + 4);
        Xs[lc + 0][lr] = x0.x; Xs[lc + 1][lr] = x0.y; Xs[lc + 2][lr] = x0.z; Xs[lc + 3][lr] = x0.w;
        Xs[lc + 4][lr] = x1.x; Xs[lc + 5][lr] = x1.y; Xs[lc + 6][lr] = x1.z; Xs[lc + 7][lr] = x1.w;
        Ws[lc + 0][lr] = w0.x; Ws[lc + 1][lr] = w0.y; Ws[lc + 2][lr] = w0.z; Ws[lc + 3][lr] = w0.w;
        Ws[lc + 4][lr] = w1.x; Ws[lc + 5][lr] = w1.y; Ws[lc + 6][lr] = w1.z; Ws[lc + 7][lr] = w1.w;
        __syncthreads();
#pragma unroll
        for (int kk = 0; kk < 16; kk++) {
            float4 a0 = *(const float4*)&Xs[kk][ty * 4];
            float4 a1 = *(const float4*)&Xs[kk][64 + ty * 4];
            float4 b0 = *(const float4*)&Ws[kk][tx * 4];
            float4 b1 = *(const float4*)&Ws[kk][64 + tx * 4];
            u64 bp[2][2] = {{pack2(b0.x, b0.y), pack2(b0.z, b0.w)},
                            {pack2(b1.x, b1.y), pack2(b1.z, b1.w)}};
            float av[2][4] = {{a0.x, a0.y, a0.z, a0.w}, {a1.x, a1.y, a1.z, a1.w}};
#pragma unroll
            for (int iq = 0; iq < 2; iq++)
#pragma unroll
                for (int i = 0; i < 4; i++) {
                    u64 ad = pack2(av[iq][i], av[iq][i]);
#pragma unroll
                    for (int jq = 0; jq < 2; jq++) {
                        acc[iq][jq][i][0] = ffma2(ad, bp[jq][0], acc[iq][jq][i][0]);
                        acc[iq][jq][i][1] = ffma2(ad, bp[jq][1], acc[iq][jq][i][1]);
                    }
                }
        }
        __syncthreads();
    }

    float4 bb0 = *(const float4*)(bsel + (tx << 2));
    float4 bb1 = *(const float4*)(bsel + 64 + (tx << 2));

    if (MODE == 0) {
#pragma unroll
        for (int iq = 0; iq < 2; iq++)
#pragma unroll
            for (int i = 0; i < 4; i++) {
                int r = bm + iq * 64 + ty * 4 + i;
#pragma unroll
                for (int jq = 0; jq < 2; jq++) {
                    int c = bn + jq * 64 + (tx << 2);
                    float4 bb = jq ? bb1 : bb0;
                    float2 p0 = unpack2(acc[iq][jq][i][0]);
                    float2 p1 = unpack2(acc[iq][jq][i][1]);
                    *(float4*)(out0 + (size_t)r * N + c) =
                        make_float4(p0.x + bb.x, p0.y + bb.y, p1.x + bb.z, p1.y + bb.w);
                }
            }
    } else {
        const bool do_norm = isQ || (bn < 512);
#pragma unroll
        for (int iq = 0; iq < 2; iq++)
#pragma unroll
            for (int i = 0; i < 4; i++) {
                int r = bm + iq * 64 + ty * 4 + i;
                int b, nn;
                if (isQ) { b = r >> 8; nn = r & 255; }
                else     { b = r / N2; nn = r - b * N2; }
#pragma unroll
                for (int jq = 0; jq < 2; jq++) {
                    float4 bb = jq ? bb1 : bb0;
                    float2 p0 = unpack2(acc[iq][jq][i][0]);
                    float2 p1 = unpack2(acc[iq][jq][i][1]);
                    float v0 = p0.x + bb.x, v1 = p0.y + bb.y;
                    float v2 = p1.x + bb.z, v3 = p1.y + bb.w;
                    float s = 1.f;
                    if (do_norm) {
                        float ss = v0 * v0 + v1 * v1 + v2 * v2 + v3 * v3;
                        ss += __shfl_xor_sync(0xffffffffu, ss, 1);
                        ss += __shfl_xor_sync(0xffffffffu, ss, 2);
                        ss += __shfl_xor_sync(0xffffffffu, ss, 4);
                        ss += __shfl_xor_sync(0xffffffffu, ss, 8);
                        s = 1.0f / fmaxf(sqrtf(ss), 1e-12f);
                    }
                    int c0 = bn + jq * 64;
                    float* dst;
                    if (isQ) {
                        int h = c0 >> 6;
                        dst = out2 + ((size_t)((b * H + h) * N1 + nn)) * 64 + (tx << 2);
                    } else if (c0 < 512) {
                        int h = c0 >> 6;
                        dst = out0 + ((size_t)((b * H + h) * N2 + nn)) * 64 + (tx << 2);
                    } else {
                        int h = (c0 - 512) >> 6;
                        dst = out1 + ((size_t)((b * H + h) * N2 + nn)) * 64 + (tx << 2);
                    }
                    *(float4*)dst = make_float4(v0 * s, v1 * s, v2 * s, v3 * s);
                }
            }
    }
}

// ---------------------------------------------------------------------------
// sim = q.k (beta_t=1); store fp16 A = exp(20*sim-9) and fp16 P = sim*A.
// 128(i) x 64(j) tiles, 8x4 per thread. Dynamic smem ~51KB.
// ---------------------------------------------------------------------------
constexpr int SIM_SMEM_BYTES = (64 * 132 + 64 * 68) * 4;

__global__ __launch_bounds__(256) void sim_kernel(
    const float* __restrict__ q, const float* __restrict__ k,
    __half* __restrict__ Ao, __half* __restrict__ Po)
{
    extern __shared__ __align__(16) float ssm[];
    float (*Qs)[132] = (float(*)[132])ssm;            // [kk][i] 64x132
    float (*Ks)[68]  = (float(*)[68])(ssm + 64 * 132); // [kk][j] 64x68

    int bh = blockIdx.z;
    int i0 = blockIdx.y * 128, j0 = blockIdx.x * 64;
    const float* qp = q + (size_t)bh * N1 * HD;
    const float* kp = k + (size_t)bh * N2 * HD;
    int tid = threadIdx.x;
    int tx = tid & 15, ty = tid >> 4;

    // load Q tile: 128 rows x 64 cols; 2 threads per row, 8 float4 each
    {
        int lr = tid >> 1;
        int c8 = (tid & 1) * 8;
#pragma unroll
        for (int it = 0; it < 8; it++) {
            int lc = (c8 + it) * 4;
            float4 qv = *(const float4*)(qp + (size_t)(i0 + lr) * HD + lc);
            Qs[lc + 0][lr] = qv.x; Qs[lc + 1][lr] = qv.y;
            Qs[lc + 2][lr] = qv.z; Qs[lc + 3][lr] = qv.w;
        }
    }
    // load K tile: 64 rows x 64 cols; 4 threads per row, 4 float4 each
    {
        int lr = tid >> 2;
#pragma unroll
        for (int it = 0; it < 4; it++) {
            int lc = (((tid & 3) + (it << 2)) << 2);
            float4 kv = *(const float4*)(kp + (size_t)(j0 + lr) * HD + lc);
            Ks[lc + 0][lr] = kv.x; Ks[lc + 1][lr] = kv.y;
            Ks[lc + 2][lr] = kv.z; Ks[lc + 3][lr] = kv.w;
        }
    }
    __syncthreads();

    u64 acc2[2][4][2];
#pragma unroll
    for (int iq = 0; iq < 2; iq++)
#pragma unroll
        for (int i = 0; i < 4; i++) { acc2[iq][i][0] = 0ull; acc2[iq][i][1] = 0ull; }

#pragma unroll 8
    for (int kk = 0; kk < 64; kk++) {
        float4 a0 = *(const float4*)&Qs[kk][ty << 2];
        float4 a1 = *(const float4*)&Qs[kk][64 + (ty << 2)];
        float4 b  = *(const float4*)&Ks[kk][tx << 2];
        u64 b01 = pack2(b.x, b.y), b23 = pack2(b.z, b.w);
        float av[2][4] = {{a0.x, a0.y, a0.z, a0.w}, {a1.x, a1.y, a1.z, a1.w}};
#pragma unroll
        for (int iq = 0; iq < 2; iq++)
#pragma unroll
            for (int i = 0; i < 4; i++) {
                u64 ad = pack2(av[iq][i], av[iq][i]);
                acc2[iq][i][0] = ffma2(ad, b01, acc2[iq][i][0]);
                acc2[iq][i][1] = ffma2(ad, b23, acc2[iq][i][1]);
            }
    }
    size_t base = (size_t)bh * N1 * N2;
#pragma unroll
    for (int iq = 0; iq < 2; iq++)
#pragma unroll
        for (int i = 0; i < 4; i++) {
            int row = i0 + iq * 64 + (ty << 2) + i;
            size_t idx = base + (size_t)row * N2 + (j0 + (tx << 2));
            float2 p0 = unpack2(acc2[iq][i][0]);
            float2 p1 = unpack2(acc2[iq][i][1]);
            float e0 = __expf(fmaf(p0.x, 20.0f, -9.0f));
            float e1 = __expf(fmaf(p0.y, 20.0f, -9.0f));
            float e2 = __expf(fmaf(p1.x, 20.0f, -9.0f));
            float e3 = __expf(fmaf(p1.y, 20.0f, -9.0f));
            __half2* A2 = (__half2*)(Ao + idx);
            A2[0] = __floats2half2_rn(e0, e1);
            A2[1] = __floats2half2_rn(e2, e3);
            __half2* P2 = (__half2*)(Po + idx);
            P2[0] = __floats2half2_rn(p0.x * e0, p0.y * e1);
            P2[1] = __floats2half2_rn(p1.x * e2, p1.y * e3);
        }
}

// ---------------------------------------------------------------------------
// Sinkhorn, fp16 shifted A, ONE CTA of 1024 threads (32 warps) per bh slice.
// Proven structure (8 rows/warp, unroll 4); exact bit-trick fp16->f32x2 with
// 2^56 compensation folded into MU/NU.
// ---------------------------------------------------------------------------
constexpr int SK_THREADS = 1024;
constexpr int SK_NW = SK_THREADS / 32;          // 32 warps
constexpr int SK_RPW = N1 / SK_NW;              // 8 rows per warp
constexpr int SK_CP_STRIDE = 584;               // padded col-partial stride
constexpr int SK_OFF_ALPHA = 0;                 // [256]
constexpr int SK_OFF_R     = 256;               // [256]
constexpr int SK_OFF_BETA  = 512;               // [576] (8B aligned)
constexpr int SK_OFF_CP    = 1088;              // [32][584]
constexpr int SK_SMEM_FLOATS = SK_OFF_CP + SK_NW * SK_CP_STRIDE;
constexpr int SK_SMEM_BYTES  = SK_SMEM_FLOATS * 4;   // ~79KB

__global__ __launch_bounds__(SK_THREADS, 1) void sinkhorn_kernel(
    const __half* __restrict__ A16, float* __restrict__ alpha_out,
    float* __restrict__ beta_out)
{
    extern __shared__ __align__(16) float smem[];
    float* s_alpha = smem + SK_OFF_ALPHA;
    float* s_r     = smem + SK_OFF_R;
    float* s_beta  = smem + SK_OFF_BETA;
    float* s_cpart = smem + SK_OFF_CP;

    int bh = blockIdx.x;
    const u32* A = (const u32*)(A16 + (size_t)bh * N1 * N2);  // 288 u32 per row
    int tid = threadIdx.x, lane = tid & 31, w = tid >> 5;

    for (int i = tid; i < N1; i += SK_THREADS) s_alpha[i] = 1.f;
    for (int j = tid; j < N2; j += SK_THREADS) s_beta[j] = 1.f;
    __syncthreads();

    const float SC56  = 7.2057594037927936e16f;   // 2^56 (exact)
    const float MU_S  = (1.0f / 256.0f + 1e-8f) * 1.3877787807814457e-17f;  // MU * 2^-56
    const float NU_S  = (1.0f / 576.0f + 1e-8f) * 1.3877787807814457e-17f;  // NU * 2^-56
    const u64 C56 = pack2(SC56, SC56);
    const u64 ZERO2 = 0ull;

#pragma unroll 1
    for (int it = 0; it < ITERS; it++) {
        u64 pb[9], pc[9];
        const u64* sb2 = (const u64*)s_beta;
#pragma unroll
        for (int t = 0; t < 9; t++) {
            pb[t] = ffma2(sb2[lane + 32 * t], C56, ZERO2);   // beta * 2^56
            pc[t] = 0ull;
        }

#pragma unroll 4
        for (int rr = 0; rr < SK_RPW; rr++) {
            int i = w * SK_RPW + rr;
            float ais = s_alpha[i] * SC56;                   // alpha * 2^56
            u64 ad = pack2(ais, ais);
            u64 accr2 = 0ull;
            const u32* row = A + i * 288 + lane;
#pragma unroll
            for (int t = 0; t < 9; t++) {
                u32 x = row[32 * t];
                u32 lo = (x << 13) & 0x1fffe000u;            // h0 -> f32 bits * 2^-112
                u32 hi = (x >> 3)  & 0x1fffe000u;            // h1 -> f32 bits * 2^-112
                u64 a2 = ((u64)hi << 32) | (u64)lo;
                accr2 = ffma2(a2, pb[t], accr2);             // (A*2^-112)(b*2^56) = Ab*2^-56
                pc[t] = ffma2(a2, ad, pc[t]);                // col parts * 2^-56
            }
            float2 ar = unpack2(accr2);
            float accr = ar.x + ar.y;
#pragma unroll
            for (int o = 16; o > 0; o >>= 1) accr += __shfl_xor_sync(0xffffffffu, accr, o);
            if (lane == 0) s_r[i] = accr;                    // rowsum * 2^-56
        }
        u64* cp2 = (u64*)(s_cpart + w * SK_CP_STRIDE);
#pragma unroll
        for (int t = 0; t < 9; t++) cp2[lane + 32 * t] = pc[t];
        __syncthreads();

        if (tid < N1) s_alpha[tid] = MU_S / s_r[tid];        // = MU / rowsum (true alpha)
        if (tid < N2) {
            float sc = 0.f;
#pragma unroll
            for (int ww = 0; ww < SK_NW; ww++) sc += s_cpart[ww * SK_CP_STRIDE + tid];
            s_beta[tid] = NU_S / sc;                         // = NU / colsum (true beta)
        }
        __syncthreads();
    }

    for (int i = tid; i < N1; i += SK_THREADS) alpha_out[bh * N1 + i] = s_alpha[i];
    for (int j = tid; j < N2; j += SK_THREADS) beta_out[bh * N2 + j] = s_beta[j];
}

// ---------------------------------------------------------------------------
// ctx = (N1*N2 * P * alpha_n * beta_m) @ v, P = fp16(sim * e^(20 sim-9)).
// Retiled 128(n) x 64(c), 256 threads, 8x4 per thread (halves LDS per FFMA2).
// Dynamic smem ~51KB.
// ---------------------------------------------------------------------------
constexpr int AV_SMEM_FLOATS = 64 * 132 + 64 * 68 + 128 + 64;
constexpr int AV_SMEM_BYTES  = AV_SMEM_FLOATS * 4;

__global__ __launch_bounds__(256) void av_kernel(
    const __half* __restrict__ P_all, const float* __restrict__ v_all,
    const float* __restrict__ alpha, const float* __restrict__ beta,
    float* __restrict__ ctx)
{
    extern __shared__ __align__(16) float avsm[];
    float (*Ss)[132] = (float(*)[132])avsm;                   // [m][n] 64x132
    float (*Vs)[68]  = (float(*)[68])(avsm + 64 * 132);       // [m][c] 64x68
    float* sa = avsm + 64 * 132 + 64 * 68;                    // [128]
    float* sb = sa + 128;                                     // [64]

    int bh = blockIdx.y;
    int n0 = blockIdx.x * 128;
    const __half* Pp = P_all + (size_t)bh * N1 * N2;
    const float* vp  = v_all + (size_t)bh * N2 * HD;
    int tid = threadIdx.x, tx = tid & 15, ty = tid >> 4;
    const int plr = tid >> 1;            // 0..127  (n row for P staging)
    const int pc8 = (tid & 1) * 8;       // 0 or 8  (m quad offset)
    const int vlr = tid >> 2;            // 0..63   (m row for V staging)

    if (tid < 128) sa[tid] = alpha[bh * N1 + n0 + tid] * 147456.0f;  // fold N1*N2

    u64 acc2[2][4][2];
#pragma unroll
    for (int iq = 0; iq < 2; iq++)
#pragma unroll
        for (int i = 0; i < 4; i++) { acc2[iq][i][0] = 0ull; acc2[iq][i][1] = 0ull; }

    for (int m0 = 0; m0 < N2; m0 += 64) {
        if (tid < 64) sb[tid] = beta[bh * N2 + m0 + tid];
        __syncthreads();          // sa/sb visible + previous compute done
        // stage Ss: 128 n-rows x 64 m; 2 threads per n-row, 8 u64 P loads each
        {
            float an = sa[plr];
#pragma unroll
            for (int it = 0; it < 8; it++) {
                int lc = (pc8 + it) * 4;   // m offset
                u64 ph = *(const u64*)(Pp + (size_t)(n0 + plr) * N2 + m0 + lc);
                float2 f01 = __half22float2(*(const __half2*)&ph);
                u32 phh = (u32)(ph >> 32);
                float2 f23 = __half22float2(*(const __half2*)&phh);
                Ss[lc + 0][plr] = f01.x * an * sb[lc + 0];
                Ss[lc + 1][plr] = f01.y * an * sb[lc + 1];
                Ss[lc + 2][plr] = f23.x * an * sb[lc + 2];
                Ss[lc + 3][plr] = f23.y * an * sb[lc + 3];
            }
        }
        // stage Vs: 64 m-rows x 64 c; 4 threads per row, 4 float4 each
#pragma unroll
        for (int it = 0; it < 4; it++) {
            int lc = (((tid & 3) + (it << 2)) << 2);
            float4 vv = *(const float4*)(vp + (size_t)(m0 + vlr) * HD + lc);
            *(float4*)&Vs[vlr][lc] = vv;
        }
        __syncthreads();
#pragma unroll 8
        for (int kk = 0; kk < 64; kk++) {
            float4 a0 = *(const float4*)&Ss[kk][ty << 2];
            float4 a1 = *(const float4*)&Ss[kk][64 + (ty << 2)];
            float4 b  = *(const float4*)&Vs[kk][tx << 2];
            u64 b01 = pack2(b.x, b.y), b23 = pack2(b.z, b.w);
            float av[2][4] = {{a0.x, a0.y, a0.z, a0.w}, {a1.x, a1.y, a1.z, a1.w}};
#pragma unroll
            for (int iq = 0; iq < 2; iq++)
#pragma unroll
                for (int i = 0; i < 4; i++) {
                    u64 ad = pack2(av[iq][i], av[iq][i]);
                    acc2[iq][i][0] = ffma2(ad, b01, acc2[iq][i][0]);
                    acc2[iq][i][1] = ffma2(ad, b23, acc2[iq][i][1]);
                }
        }
    }
    int b = bh >> 3, h = bh & 7;
#pragma unroll
    for (int iq = 0; iq < 2; iq++)
#pragma unroll
        for (int i = 0; i < 4; i++) {
            int n = n0 + iq * 64 + (ty << 2) + i;
            float2 p0 = unpack2(acc2[iq][i][0]);
            float2 p1 = unpack2(acc2[iq][i][1]);
            float* dst = ctx + (size_t)(b * N1 + n) * DIM + h * HD + (tx << 2);
            *(float4*)dst = make_float4(p0.x, p0.y, p1.x, p1.y);
        }
}

// ---------------------------------------------------------------------------
// In-place row L2 normalization (plain divide): rows of 512 floats
// ---------------------------------------------------------------------------
__global__ __launch_bounds__(128) void norm_rows_kernel(float* __restrict__ out)
{
    __shared__ float red[4];
    int row = blockIdx.x;
    float4* p = (float4*)(out + (size_t)row * DIM);
    int tid = threadIdx.x;
    float4 v = p[tid];
    float ss = v.x * v.x + v.y * v.y + v.z * v.z + v.w * v.w;
#pragma unroll
    for (int o = 16; o > 0; o >>= 1) ss += __shfl_xor_sync(0xffffffffu, ss, o);
    if ((tid & 31) == 0) red[tid >> 5] = ss;
    __syncthreads();
    float tot = red[0] + red[1] + red[2] + red[3];
    float inv = 1.0f / sqrtf(tot);
    v.x *= inv; v.y *= inv; v.z *= inv; v.w *= inv;
    p[tid] = v;
}

// ---------------------------------------------------------------------------
extern "C" void kernel_launch(void* const* d_in, const int* in_sizes, int n_in,
                              void* d_out, int out_size)
{
    (void)in_sizes; (void)n_in; (void)out_size;
    const float* F_t = (const float*)d_in[0];
    const float* F_s = (const float*)d_in[1];
    const float* Wq  = (const float*)d_in[2];
    const float* bq  = (const float*)d_in[3];
    const float* Wk  = (const float*)d_in[4];
    const float* bk  = (const float*)d_in[5];
    const float* Wv  = (const float*)d_in[6];
    const float* bv  = (const float*)d_in[7];
    const float* Wp  = (const float*)d_in[8];
    const float* bp  = (const float*)d_in[9];
    float* out = (float*)d_out;

    float *q, *k, *v, *alpha, *beta, *ctx;
    __half *A16, *P16;
    cudaGetSymbolAddress((void**)&q, g_q);
    cudaGetSymbolAddress((void**)&k, g_k);
    cudaGetSymbolAddress((void**)&v, g_v);
    cudaGetSymbolAddress((void**)&A16, g_A16);
    cudaGetSymbolAddress((void**)&P16, g_P16);
    cudaGetSymbolAddress((void**)&alpha, g_alpha);
    cudaGetSymbolAddress((void**)&beta, g_beta);
    cudaGetSymbolAddress((void**)&ctx, g_ctx);

    // dynamic smem attributes (host API, capture-safe; proven since R7)
    cudaFuncSetAttribute(sinkhorn_kernel,
                         cudaFuncAttributeMaxDynamicSharedMemorySize, SK_SMEM_BYTES);
    cudaFuncSetAttribute(sim_kernel,
                         cudaFuncAttributeMaxDynamicSharedMemorySize, SIM_SMEM_BYTES);
    cudaFuncSetAttribute(av_kernel,
                         cudaFuncAttributeMaxDynamicSharedMemorySize, AV_SMEM_BYTES);

    // 1+2) fused QKV projections (+ transpose, + l2norm for q,k) in ONE launch
    gemm128_kernel<3><<<dim3(8, 104), 256>>>(
        F_s, F_t, Wk, Wv, Wq, bk, bv, bq, k, v, q, 0, 0, DIM);

    // 3) sim -> fp16 A (Sinkhorn) + fp16 P (av); 128x64 tiles
    sim_kernel<<<dim3(N2 / 64, N1 / 128, BH), 256, SIM_SMEM_BYTES>>>(q, k, A16, P16);

    // 4) 100 Sinkhorn iterations, one 1024-thread CTA per (b,h)
    sinkhorn_kernel<<<BH, SK_THREADS, SK_SMEM_BYTES>>>(A16, alpha, beta);

    // 5) score @ v -> ctx [B*N1, 512]; 128x64 tiles
    av_kernel<<<dim3(N1 / 128, BH), 256, AV_SMEM_BYTES>>>(P16, v, alpha, beta, ctx);

    // 6) projection + 7) row normalize (in place in d_out)
    gemm128_kernel<0><<<dim3(DIM / 128, B * N1 / 128), 256>>>(
        ctx, nullptr, Wp, nullptr, nullptr, bp, nullptr, nullptr,
        out, nullptr, nullptr, B * N1, DIM, DIM);
    norm_rows_kernel<<<B * N1, 128>>>(out);
}

// round 15
// speedup vs baseline: 1.7635x; 1.0421x over previous
#include <cuda_runtime.h>
#include <cuda_fp16.h>
#include <math.h>

// Problem constants
constexpr int B   = 16;
constexpr int H   = 8;
constexpr int N1  = 256;
constexpr int N2  = 576;
constexpr int HD  = 64;
constexpr int DIM = 512;
constexpr int BH  = B * H;       // 128
constexpr int ITERS = 100;

typedef unsigned long long u64;
typedef unsigned int u32;

// ---- packed f32x2 helpers (sm_103a FFMA2; ptxas never auto-fuses) ----
__device__ __forceinline__ u64 ffma2(u64 a, u64 b, u64 c) {
    u64 d; asm("fma.rn.f32x2 %0,%1,%2,%3;" : "=l"(d) : "l"(a), "l"(b), "l"(c)); return d;
}
__device__ __forceinline__ u64 pack2(float x, float y) {
    u64 d; asm("mov.b64 %0,{%1,%2};" : "=l"(d) : "f"(x), "f"(y)); return d;
}
__device__ __forceinline__ float2 unpack2(u64 d) {
    float2 r; asm("mov.b64 {%0,%1},%2;" : "=f"(r.x), "=f"(r.y) : "l"(d)); return r;
}

// Static scratch (no runtime allocation allowed)
__device__ float g_q[BH * N1 * HD];
__device__ float g_k[BH * N2 * HD];
__device__ float g_v[BH * N2 * HD];
__device__ __half g_A16[(size_t)BH * N1 * N2];   // fp16 shifted Gibbs kernel e^(20 sim - 9)
__device__ __half g_P16[(size_t)BH * N1 * N2];   // fp16 sim * e^(20 sim - 9)  (for av)
__device__ float g_alpha[BH * N1];
__device__ float g_beta[BH * N2];
__device__ float g_ctx[B * N1 * DIM];

// ---------------------------------------------------------------------------
// fp32 GEMM, 128x128 tile, 256 threads, 8x8/thread, FFMA2 inner product,
// DOUBLE-BUFFERED smem mainloop (1 barrier/step, LDG overlaps compute).
// MODE 0: plain  out0[M,N] = X@W0^T + bias0   (grid (N/128, M/128))
// MODE 3: fused QKV. grid (8, 104):
//   by <  72 : KV CTA (F_s rows); bn<512 -> K (norm, out0), else V (out1).
//   by >= 72 : Q CTA (bx<4, F_t rows), norm, out2.
// ---------------------------------------------------------------------------
template<int MODE>
__global__ __launch_bounds__(256) void gemm128_kernel(
    const float* __restrict__ X,  const float* __restrict__ X2,
    const float* __restrict__ W0, const float* __restrict__ W1,
    const float* __restrict__ W2,
    const float* __restrict__ bias0, const float* __restrict__ bias1,
    const float* __restrict__ bias2,
    float* __restrict__ out0, float* __restrict__ out1,
    float* __restrict__ out2,
    int M, int N, int K)
{
    const int bx = blockIdx.x, by = blockIdx.y;
    bool isQ = false;
    int bm, bn = bx * 128;
    if (MODE == 3) {
        isQ = (by >= 72);
        if (isQ && bx >= 4) return;      // Q only spans 512 cols
        bm = isQ ? (by - 72) * 128 : by * 128;
    } else {
        bm = by * 128;
    }

    __shared__ __align__(16) float Xs0[16][132], Xs1[16][132];
    __shared__ __align__(16) float Ws0[16][132], Ws1[16][132];
    const int tid = threadIdx.x;
    const int tx = tid & 15, ty = tid >> 4;
    const int lr = tid >> 1;            // 0..127
    const int lc = (tid & 1) * 8;       // 0 or 8

    const float* Xbase = (MODE == 3 && isQ) ? X2 : X;
    const float* Wsel;
    const float* bsel;
    if (MODE == 3 && isQ)            { Wsel = W2 + (size_t)bn * K;         bsel = bias2 + bn; }
    else if (MODE == 3 && bn >= 512) { Wsel = W1 + (size_t)(bn - 512) * K; bsel = bias1 + (bn - 512); }
    else                             { Wsel = W0 + (size_t)bn * K;         bsel = bias0 + bn; }

    u64 acc[2][2][4][2];
#pragma unroll
    for (int iq = 0; iq < 2; iq++)
#pragma unroll
        for (int jq = 0; jq < 2; jq++)
#pragma unroll
            for (int i = 0; i < 4; i++) { acc[iq][jq][i][0] = 0ull; acc[iq][jq][i][1] = 0ull; }

    const float* Xp = Xbase + (size_t)(bm + lr) * K + lc;
    const float* Wp = Wsel + (size_t)lr * K + lc;

    float (*Xc)[132] = Xs0; float (*Xn)[132] = Xs1;
    float (*Wc)[132] = Ws0; float (*Wn)[132] = Ws1;

    // preload step 0 into current buffers
    {
        float4 x0 = *(const float4*)(Xp);
        float4 x1 = *(const float4*)(Xp + 4);
        float4 w0 = *(const float4*)(Wp);
        float4 w1 = *(const float4*)(Wp + 4);
        Xc[lc + 0][lr] = x0.x; Xc[lc + 1][lr] = x0.y; Xc[lc + 2][lr] = x0.z; Xc[lc + 3][lr] = x0.w;
        Xc[lc + 4][lr] = x1.x; Xc[lc + 5][lr] = x1.y; Xc[lc + 6][lr] = x1.z; Xc[lc + 7][lr] = x1.w;
        Wc[lc + 0][lr] = w0.x; Wc[lc + 1][lr] = w0.y; Wc[lc + 2][lr] = w0.z; Wc[lc + 3][lr] = w0.w;
        Wc[lc + 4][lr] = w1.x; Wc[lc + 5][lr] = w1.y; Wc[lc + 6][lr] = w1.z; Wc[lc + 7][lr] = w1.w;
    }

    for (int k0 = 0; k0 < K; k0 += 16) {
        __syncthreads();                         // current buffer ready; prev readers done
        const bool hn = (k0 + 16 < K);
        float4 nx0, nx1, nw0, nw1;
        if (hn) {                                // LDG next tile; latency hidden by compute
            nx0 = *(const float4*)(Xp + k0 + 16);
            nx1 = *(const float4*)(Xp + k0 + 20);
            nw0 = *(const float4*)(Wp + k0 + 16);
            nw1 = *(const float4*)(Wp + k0 + 20);
        }
#pragma unroll
        for (int kk = 0; kk < 16; kk++) {
            float4 a0 = *(const float4*)&Xc[kk][ty * 4];
            float4 a1 = *(const float4*)&Xc[kk][64 + ty * 4];
            float4 b0 = *(const float4*)&Wc[kk][tx * 4];
            float4 b1 = *(const float4*)&Wc[kk][64 + tx * 4];
            u64 bp[2][2] = {{pack2(b0.x, b0.y), pack2(b0.z, b0.w)},
                            {pack2(b1.x, b1.y), pack2(b1.z, b1.w)}};
            float av[2][4] = {{a0.x, a0.y, a0.z, a0.w}, {a1.x, a1.y, a1.z, a1.w}};
#pragma unroll
            for (int iq = 0; iq < 2; iq++)
#pragma unroll
                for (int i = 0; i < 4; i++) {
                    u64 ad = pack2(av[iq][i], av[iq][i]);
#pragma unroll
                    for (int jq = 0; jq < 2; jq++) {
                        acc[iq][jq][i][0] = ffma2(ad, bp[jq][0], acc[iq][jq][i][0]);
                        acc[iq][jq][i][1] = ffma2(ad, bp[jq][1], acc[iq][jq][i][1]);
                    }
                }
        }
        if (hn) {                                // store into idle buffer; no barrier needed
            Xn[lc + 0][lr] = nx0.x; Xn[lc + 1][lr] = nx0.y; Xn[lc + 2][lr] = nx0.z; Xn[lc + 3][lr] = nx0.w;
            Xn[lc + 4][lr] = nx1.x; Xn[lc + 5][lr] = nx1.y; Xn[lc + 6][lr] = nx1.z; Xn[lc + 7][lr] = nx1.w;
            Wn[lc + 0][lr] = nw0.x; Wn[lc + 1][lr] = nw0.y; Wn[lc + 2][lr] = nw0.z; Wn[lc + 3][lr] = nw0.w;
            Wn[lc + 4][lr] = nw1.x; Wn[lc + 5][lr] = nw1.y; Wn[lc + 6][lr] = nw1.z; Wn[lc + 7][lr] = nw1.w;
            float (*t)[132] = Xc; Xc = Xn; Xn = t;
            float (*t2)[132] = Wc; Wc = Wn; Wn = t2;
        }
    }

    float4 bb0 = *(const float4*)(bsel + (tx << 2));
    float4 bb1 = *(const float4*)(bsel + 64 + (tx << 2));

    if (MODE == 0) {
#pragma unroll
        for (int iq = 0; iq < 2; iq++)
#pragma unroll
            for (int i = 0; i < 4; i++) {
                int r = bm + iq * 64 + ty * 4 + i;
#pragma unroll
                for (int jq = 0; jq < 2; jq++) {
                    int c = bn + jq * 64 + (tx << 2);
                    float4 bb = jq ? bb1 : bb0;
                    float2 p0 = unpack2(acc[iq][jq][i][0]);
                    float2 p1 = unpack2(acc[iq][jq][i][1]);
                    *(float4*)(out0 + (size_t)r * N + c) =
                        make_float4(p0.x + bb.x, p0.y + bb.y, p1.x + bb.z, p1.y + bb.w);
                }
            }
    } else {
        const bool do_norm = isQ || (bn < 512);
#pragma unroll
        for (int iq = 0; iq < 2; iq++)
#pragma unroll
            for (int i = 0; i < 4; i++) {
                int r = bm + iq * 64 + ty * 4 + i;
                int b, nn;
                if (isQ) { b = r >> 8; nn = r & 255; }
                else     { b = r / N2; nn = r - b * N2; }
#pragma unroll
                for (int jq = 0; jq < 2; jq++) {
                    float4 bb = jq ? bb1 : bb0;
                    float2 p0 = unpack2(acc[iq][jq][i][0]);
                    float2 p1 = unpack2(acc[iq][jq][i][1]);
                    float v0 = p0.x + bb.x, v1 = p0.y + bb.y;
                    float v2 = p1.x + bb.z, v3 = p1.y + bb.w;
                    float s = 1.f;
                    if (do_norm) {
                        float ss = v0 * v0 + v1 * v1 + v2 * v2 + v3 * v3;
                        ss += __shfl_xor_sync(0xffffffffu, ss, 1);
                        ss += __shfl_xor_sync(0xffffffffu, ss, 2);
                        ss += __shfl_xor_sync(0xffffffffu, ss, 4);
                        ss += __shfl_xor_sync(0xffffffffu, ss, 8);
                        s = 1.0f / fmaxf(sqrtf(ss), 1e-12f);
                    }
                    int c0 = bn + jq * 64;
                    float* dst;
                    if (isQ) {
                        int h = c0 >> 6;
                        dst = out2 + ((size_t)((b * H + h) * N1 + nn)) * 64 + (tx << 2);
                    } else if (c0 < 512) {
                        int h = c0 >> 6;
                        dst = out0 + ((size_t)((b * H + h) * N2 + nn)) * 64 + (tx << 2);
                    } else {
                        int h = (c0 - 512) >> 6;
                        dst = out1 + ((size_t)((b * H + h) * N2 + nn)) * 64 + (tx << 2);
                    }
                    *(float4*)dst = make_float4(v0 * s, v1 * s, v2 * s, v3 * s);
                }
            }
    }
}

// ---------------------------------------------------------------------------
// sim = q.k (beta_t=1); store fp16 A = exp(20*sim-9) and fp16 P = sim*A.
// 128(i) x 64(j) tiles, 8x4 per thread. Dynamic smem ~51KB.
// ---------------------------------------------------------------------------
constexpr int SIM_SMEM_BYTES = (64 * 132 + 64 * 68) * 4;

__global__ __launch_bounds__(256) void sim_kernel(
    const float* __restrict__ q, const float* __restrict__ k,
    __half* __restrict__ Ao, __half* __restrict__ Po)
{
    extern __shared__ __align__(16) float ssm[];
    float (*Qs)[132] = (float(*)[132])ssm;            // [kk][i] 64x132
    float (*Ks)[68]  = (float(*)[68])(ssm + 64 * 132); // [kk][j] 64x68

    int bh = blockIdx.z;
    int i0 = blockIdx.y * 128, j0 = blockIdx.x * 64;
    const float* qp = q + (size_t)bh * N1 * HD;
    const float* kp = k + (size_t)bh * N2 * HD;
    int tid = threadIdx.x;
    int tx = tid & 15, ty = tid >> 4;

    // load Q tile: 128 rows x 64 cols; 2 threads per row, 8 float4 each
    {
        int lr = tid >> 1;
        int c8 = (tid & 1) * 8;
#pragma unroll
        for (int it = 0; it < 8; it++) {
            int lc = (c8 + it) * 4;
            float4 qv = *(const float4*)(qp + (size_t)(i0 + lr) * HD + lc);
            Qs[lc + 0][lr] = qv.x; Qs[lc + 1][lr] = qv.y;
            Qs[lc + 2][lr] = qv.z; Qs[lc + 3][lr] = qv.w;
        }
    }
    // load K tile: 64 rows x 64 cols; 4 threads per row, 4 float4 each
    {
        int lr = tid >> 2;
#pragma unroll
        for (int it = 0; it < 4; it++) {
            int lc = (((tid & 3) + (it << 2)) << 2);
            float4 kv = *(const float4*)(kp + (size_t)(j0 + lr) * HD + lc);
            Ks[lc + 0][lr] = kv.x; Ks[lc + 1][lr] = kv.y;
            Ks[lc + 2][lr] = kv.z; Ks[lc + 3][lr] = kv.w;
        }
    }
    __syncthreads();

    u64 acc2[2][4][2];
#pragma unroll
    for (int iq = 0; iq < 2; iq++)
#pragma unroll
        for (int i = 0; i < 4; i++) { acc2[iq][i][0] = 0ull; acc2[iq][i][1] = 0ull; }

#pragma unroll 8
    for (int kk = 0; kk < 64; kk++) {
        float4 a0 = *(const float4*)&Qs[kk][ty << 2];
        float4 a1 = *(const float4*)&Qs[kk][64 + (ty << 2)];
        float4 b  = *(const float4*)&Ks[kk][tx << 2];
        u64 b01 = pack2(b.x, b.y), b23 = pack2(b.z, b.w);
        float av[2][4] = {{a0.x, a0.y, a0.z, a0.w}, {a1.x, a1.y, a1.z, a1.w}};
#pragma unroll
        for (int iq = 0; iq < 2; iq++)
#pragma unroll
            for (int i = 0; i < 4; i++) {
                u64 ad = pack2(av[iq][i], av[iq][i]);
                acc2[iq][i][0] = ffma2(ad, b01, acc2[iq][i][0]);
                acc2[iq][i][1] = ffma2(ad, b23, acc2[iq][i][1]);
            }
    }
    size_t base = (size_t)bh * N1 * N2;
#pragma unroll
    for (int iq = 0; iq < 2; iq++)
#pragma unroll
        for (int i = 0; i < 4; i++) {
            int row = i0 + iq * 64 + (ty << 2) + i;
            size_t idx = base + (size_t)row * N2 + (j0 + (tx << 2));
            float2 p0 = unpack2(acc2[iq][i][0]);
            float2 p1 = unpack2(acc2[iq][i][1]);
            float e0 = __expf(fmaf(p0.x, 20.0f, -9.0f));
            float e1 = __expf(fmaf(p0.y, 20.0f, -9.0f));
            float e2 = __expf(fmaf(p1.x, 20.0f, -9.0f));
            float e3 = __expf(fmaf(p1.y, 20.0f, -9.0f));
            __half2* A2 = (__half2*)(Ao + idx);
            A2[0] = __floats2half2_rn(e0, e1);
            A2[1] = __floats2half2_rn(e2, e3);
            __half2* P2 = (__half2*)(Po + idx);
            P2[0] = __floats2half2_rn(p0.x * e0, p0.y * e1);
            P2[1] = __floats2half2_rn(p1.x * e2, p1.y * e3);
        }
}

// ---------------------------------------------------------------------------
// Sinkhorn, fp16 shifted A, ONE CTA of 1024 threads (32 warps) per bh slice.
// Proven structure (8 rows/warp, unroll 4); exact bit-trick fp16->f32x2 with
// 2^56 compensation folded into MU/NU.
// ---------------------------------------------------------------------------
constexpr int SK_THREADS = 1024;
constexpr int SK_NW = SK_THREADS / 32;          // 32 warps
constexpr int SK_RPW = N1 / SK_NW;              // 8 rows per warp
constexpr int SK_CP_STRIDE = 584;               // padded col-partial stride
constexpr int SK_OFF_ALPHA = 0;                 // [256]
constexpr int SK_OFF_R     = 256;               // [256]
constexpr int SK_OFF_BETA  = 512;               // [576] (8B aligned)
constexpr int SK_OFF_CP    = 1088;              // [32][584]
constexpr int SK_SMEM_FLOATS = SK_OFF_CP + SK_NW * SK_CP_STRIDE;
constexpr int SK_SMEM_BYTES  = SK_SMEM_FLOATS * 4;   // ~79KB

__global__ __launch_bounds__(SK_THREADS, 1) void sinkhorn_kernel(
    const __half* __restrict__ A16, float* __restrict__ alpha_out,
    float* __restrict__ beta_out)
{
    extern __shared__ __align__(16) float smem[];
    float* s_alpha = smem + SK_OFF_ALPHA;
    float* s_r     = smem + SK_OFF_R;
    float* s_beta  = smem + SK_OFF_BETA;
    float* s_cpart = smem + SK_OFF_CP;

    int bh = blockIdx.x;
    const u32* A = (const u32*)(A16 + (size_t)bh * N1 * N2);  // 288 u32 per row
    int tid = threadIdx.x, lane = tid & 31, w = tid >> 5;

    for (int i = tid; i < N1; i += SK_THREADS) s_alpha[i] = 1.f;
    for (int j = tid; j < N2; j += SK_THREADS) s_beta[j] = 1.f;
    __syncthreads();

    const float SC56  = 7.2057594037927936e16f;   // 2^56 (exact)
    const float MU_S  = (1.0f / 256.0f + 1e-8f) * 1.3877787807814457e-17f;  // MU * 2^-56
    const float NU_S  = (1.0f / 576.0f + 1e-8f) * 1.3877787807814457e-17f;  // NU * 2^-56
    const u64 C56 = pack2(SC56, SC56);
    const u64 ZERO2 = 0ull;

#pragma unroll 1
    for (int it = 0; it < ITERS; it++) {
        u64 pb[9], pc[9];
        const u64* sb2 = (const u64*)s_beta;
#pragma unroll
        for (int t = 0; t < 9; t++) {
            pb[t] = ffma2(sb2[lane + 32 * t], C56, ZERO2);   // beta * 2^56
            pc[t] = 0ull;
        }

#pragma unroll 4
        for (int rr = 0; rr < SK_RPW; rr++) {
            int i = w * SK_RPW + rr;
            float ais = s_alpha[i] * SC56;                   // alpha * 2^56
            u64 ad = pack2(ais, ais);
            u64 accr2 = 0ull;
            const u32* row = A + i * 288 + lane;
#pragma unroll
            for (int t = 0; t < 9; t++) {
                u32 x = row[32 * t];
                u32 lo = (x << 13) & 0x1fffe000u;            // h0 -> f32 bits * 2^-112
                u32 hi = (x >> 3)  & 0x1fffe000u;            // h1 -> f32 bits * 2^-112
                u64 a2 = ((u64)hi << 32) | (u64)lo;
                accr2 = ffma2(a2, pb[t], accr2);             // (A*2^-112)(b*2^56) = Ab*2^-56
                pc[t] = ffma2(a2, ad, pc[t]);                // col parts * 2^-56
            }
            float2 ar = unpack2(accr2);
            float accr = ar.x + ar.y;
#pragma unroll
            for (int o = 16; o > 0; o >>= 1) accr += __shfl_xor_sync(0xffffffffu, accr, o);
            if (lane == 0) s_r[i] = accr;                    // rowsum * 2^-56
        }
        u64* cp2 = (u64*)(s_cpart + w * SK_CP_STRIDE);
#pragma unroll
        for (int t = 0; t < 9; t++) cp2[lane + 32 * t] = pc[t];
        __syncthreads();

        if (tid < N1) s_alpha[tid] = MU_S / s_r[tid];        // = MU / rowsum (true alpha)
        if (tid < N2) {
            float sc = 0.f;
#pragma unroll
            for (int ww = 0; ww < SK_NW; ww++) sc += s_cpart[ww * SK_CP_STRIDE + tid];
            s_beta[tid] = NU_S / sc;                         // = NU / colsum (true beta)
        }
        __syncthreads();
    }

    for (int i = tid; i < N1; i += SK_THREADS) alpha_out[bh * N1 + i] = s_alpha[i];
    for (int j = tid; j < N2; j += SK_THREADS) beta_out[bh * N2 + j] = s_beta[j];
}

// ---------------------------------------------------------------------------
// ctx = (N1*N2 * P * alpha_n * beta_m) @ v, P = fp16(sim * e^(20 sim-9)).
// 128(n) x 64(c) tiles, 256 threads, 8x4 per thread. Dynamic smem ~51KB.
// ---------------------------------------------------------------------------
constexpr int AV_SMEM_FLOATS = 64 * 132 + 64 * 68 + 128 + 64;
constexpr int AV_SMEM_BYTES  = AV_SMEM_FLOATS * 4;

__global__ __launch_bounds__(256) void av_kernel(
    const __half* __restrict__ P_all, const float* __restrict__ v_all,
    const float* __restrict__ alpha, const float* __restrict__ beta,
    float* __restrict__ ctx)
{
    extern __shared__ __align__(16) float avsm[];
    float (*Ss)[132] = (float(*)[132])avsm;                   // [m][n] 64x132
    float (*Vs)[68]  = (float(*)[68])(avsm + 64 * 132);       // [m][c] 64x68
    float* sa = avsm + 64 * 132 + 64 * 68;                    // [128]
    float* sb = sa + 128;                                     // [64]

    int bh = blockIdx.y;
    int n0 = blockIdx.x * 128;
    const __half* Pp = P_all + (size_t)bh * N1 * N2;
    const float* vp  = v_all + (size_t)bh * N2 * HD;
    int tid = threadIdx.x, tx = tid & 15, ty = tid >> 4;
    const int plr = tid >> 1;            // 0..127  (n row for P staging)
    const int pc8 = (tid & 1) * 8;       // 0 or 8  (m quad offset)
    const int vlr = tid >> 2;            // 0..63   (m row for V staging)

    if (tid < 128) sa[tid] = alpha[bh * N1 + n0 + tid] * 147456.0f;  // fold N1*N2

    u64 acc2[2][4][2];
#pragma unroll
    for (int iq = 0; iq < 2; iq++)
#pragma unroll
        for (int i = 0; i < 4; i++) { acc2[iq][i][0] = 0ull; acc2[iq][i][1] = 0ull; }

    for (int m0 = 0; m0 < N2; m0 += 64) {
        if (tid < 64) sb[tid] = beta[bh * N2 + m0 + tid];
        __syncthreads();          // sa/sb visible + previous compute done
        // stage Ss: 128 n-rows x 64 m; 2 threads per n-row, 8 u64 P loads each
        {
            float an = sa[plr];
#pragma unroll
            for (int it = 0; it < 8; it++) {
                int lc = (pc8 + it) * 4;   // m offset
                u64 ph = *(const u64*)(Pp + (size_t)(n0 + plr) * N2 + m0 + lc);
                float2 f01 = __half22float2(*(const __half2*)&ph);
                u32 phh = (u32)(ph >> 32);
                float2 f23 = __half22float2(*(const __half2*)&phh);
                Ss[lc + 0][plr] = f01.x * an * sb[lc + 0];
                Ss[lc + 1][plr] = f01.y * an * sb[lc + 1];
                Ss[lc + 2][plr] = f23.x * an * sb[lc + 2];
                Ss[lc + 3][plr] = f23.y * an * sb[lc + 3];
            }
        }
        // stage Vs: 64 m-rows x 64 c; 4 threads per row, 4 float4 each
#pragma unroll
        for (int it = 0; it < 4; it++) {
            int lc = (((tid & 3) + (it << 2)) << 2);
            float4 vv = *(const float4*)(vp + (size_t)(m0 + vlr) * HD + lc);
            *(float4*)&Vs[vlr][lc] = vv;
        }
        __syncthreads();
#pragma unroll 8
        for (int kk = 0; kk < 64; kk++) {
            float4 a0 = *(const float4*)&Ss[kk][ty << 2];
            float4 a1 = *(const float4*)&Ss[kk][64 + (ty << 2)];
            float4 b  = *(const float4*)&Vs[kk][tx << 2];
            u64 b01 = pack2(b.x, b.y), b23 = pack2(b.z, b.w);
            float av[2][4] = {{a0.x, a0.y, a0.z, a0.w}, {a1.x, a1.y, a1.z, a1.w}};
#pragma unroll
            for (int iq = 0; iq < 2; iq++)
#pragma unroll
                for (int i = 0; i < 4; i++) {
                    u64 ad = pack2(av[iq][i], av[iq][i]);
                    acc2[iq][i][0] = ffma2(ad, b01, acc2[iq][i][0]);
                    acc2[iq][i][1] = ffma2(ad, b23, acc2[iq][i][1]);
                }
        }
    }
    int b = bh >> 3, h = bh & 7;
#pragma unroll
    for (int iq = 0; iq < 2; iq++)
#pragma unroll
        for (int i = 0; i < 4; i++) {
            int n = n0 + iq * 64 + (ty << 2) + i;
            float2 p0 = unpack2(acc2[iq][i][0]);
            float2 p1 = unpack2(acc2[iq][i][1]);
            float* dst = ctx + (size_t)(b * N1 + n) * DIM + h * HD + (tx << 2);
            *(float4*)dst = make_float4(p0.x, p0.y, p1.x, p1.y);
        }
}

// ---------------------------------------------------------------------------
// In-place row L2 normalization (plain divide): rows of 512 floats
// ---------------------------------------------------------------------------
__global__ __launch_bounds__(128) void norm_rows_kernel(float* __restrict__ out)
{
    __shared__ float red[4];
    int row = blockIdx.x;
    float4* p = (float4*)(out + (size_t)row * DIM);
    int tid = threadIdx.x;
    float4 v = p[tid];
    float ss = v.x * v.x + v.y * v.y + v.z * v.z + v.w * v.w;
#pragma unroll
    for (int o = 16; o > 0; o >>= 1) ss += __shfl_xor_sync(0xffffffffu, ss, o);
    if ((tid & 31) == 0) red[tid >> 5] = ss;
    __syncthreads();
    float tot = red[0] + red[1] + red[2] + red[3];
    float inv = 1.0f / sqrtf(tot);
    v.x *= inv; v.y *= inv; v.z *= inv; v.w *= inv;
    p[tid] = v;
}

// ---------------------------------------------------------------------------
extern "C" void kernel_launch(void* const* d_in, const int* in_sizes, int n_in,
                              void* d_out, int out_size)
{
    (void)in_sizes; (void)n_in; (void)out_size;
    const float* F_t = (const float*)d_in[0];
    const float* F_s = (const float*)d_in[1];
    const float* Wq  = (const float*)d_in[2];
    const float* bq  = (const float*)d_in[3];
    const float* Wk  = (const float*)d_in[4];
    const float* bk  = (const float*)d_in[5];
    const float* Wv  = (const float*)d_in[6];
    const float* bv  = (const float*)d_in[7];
    const float* Wp  = (const float*)d_in[8];
    const float* bp  = (const float*)d_in[9];
    float* out = (float*)d_out;

    float *q, *k, *v, *alpha, *beta, *ctx;
    __half *A16, *P16;
    cudaGetSymbolAddress((void**)&q, g_q);
    cudaGetSymbolAddress((void**)&k, g_k);
    cudaGetSymbolAddress((void**)&v, g_v);
    cudaGetSymbolAddress((void**)&A16, g_A16);
    cudaGetSymbolAddress((void**)&P16, g_P16);
    cudaGetSymbolAddress((void**)&alpha, g_alpha);
    cudaGetSymbolAddress((void**)&beta, g_beta);
    cudaGetSymbolAddress((void**)&ctx, g_ctx);

    // dynamic smem attributes (host API, capture-safe; proven since R7)
    cudaFuncSetAttribute(sinkhorn_kernel,
                         cudaFuncAttributeMaxDynamicSharedMemorySize, SK_SMEM_BYTES);
    cudaFuncSetAttribute(sim_kernel,
                         cudaFuncAttributeMaxDynamicSharedMemorySize, SIM_SMEM_BYTES);
    cudaFuncSetAttribute(av_kernel,
                         cudaFuncAttributeMaxDynamicSharedMemorySize, AV_SMEM_BYTES);

    // 1+2) fused QKV projections (+ transpose, + l2norm for q,k) in ONE launch
    gemm128_kernel<3><<<dim3(8, 104), 256>>>(
        F_s, F_t, Wk, Wv, Wq, bk, bv, bq, k, v, q, 0, 0, DIM);

    // 3) sim -> fp16 A (Sinkhorn) + fp16 P (av); 128x64 tiles
    sim_kernel<<<dim3(N2 / 64, N1 / 128, BH), 256, SIM_SMEM_BYTES>>>(q, k, A16, P16);

    // 4) 100 Sinkhorn iterations, one 1024-thread CTA per (b,h)
    sinkhorn_kernel<<<BH, SK_THREADS, SK_SMEM_BYTES>>>(A16, alpha, beta);

    // 5) score @ v -> ctx [B*N1, 512]; 128x64 tiles
    av_kernel<<<dim3(N1 / 128, BH), 256, AV_SMEM_BYTES>>>(P16, v, alpha, beta, ctx);

    // 6) projection + 7) row normalize (in place in d_out)
    gemm128_kernel<0><<<dim3(DIM / 128, B * N1 / 128), 256>>>(
        ctx, nullptr, Wp, nullptr, nullptr, bp, nullptr, nullptr,
        out, nullptr, nullptr, B * N1, DIM, DIM);
    norm_rows_kernel<<<B * N1, 128>>>(out);
}